// round 1
// baseline (speedup 1.0000x reference)
#include <cuda_runtime.h>
#include <math.h>

// Problem constants
#define Bx  16
#define Sx  1024
#define Hx  1024
#define Ox  256
#define Lx  4
#define NHx 8
#define DHx 128
#define Mx  (Bx*Sx)   // 16384 rows

// ---------------- scratch (device globals: no allocation allowed) ----------
__device__ float g_bufA[(size_t)Mx * Hx];   // activations (layer in/out)
__device__ float g_bufF[(size_t)Mx * Hx];   // f preact / later K
__device__ float g_bufI[(size_t)Mx * Hx];   // i preact / later V
__device__ float g_bufH[(size_t)Mx * Hx];   // h_tilde preact
__device__ float g_scores[Bx * NHx * Sx];
__device__ float g_q[Bx * Hx];
__device__ float g_o[Bx * Hx];
__device__ float g_last[Bx * Hx];

// ---------------- SGEMM: C[M,N] = A[M,K] * W[N,K]^T + bias[N] --------------
// M=16384, N=K=1024 fixed. 128x128 tile, BK=8, 256 threads, 8x8 per thread.
#define BM 128
#define BN 128
#define BK 8

__global__ __launch_bounds__(256) void sgemm_k(
    const float* __restrict__ A, const float* __restrict__ W,
    const float* __restrict__ bias, float* __restrict__ C)
{
    __shared__ float As[BK][BM];
    __shared__ float Bs[BK][BN];

    const int tid = threadIdx.x;
    const int bx = blockIdx.x;   // N tile
    const int by = blockIdx.y;   // M tile
    const int K = Hx, N = Hx;

    const float* Ab = A + (size_t)by * BM * K;
    const float* Wb = W + (size_t)bx * BN * K;

    const int lr = tid >> 1;          // 0..127 row within tile
    const int lc = (tid & 1) * 4;     // 0 or 4 within BK
    const int ty = tid >> 4;          // 0..15 -> row group
    const int tx = tid & 15;          // 0..15 -> col group

    float acc[8][8];
    #pragma unroll
    for (int i = 0; i < 8; i++)
        #pragma unroll
        for (int j = 0; j < 8; j++)
            acc[i][j] = 0.f;

    for (int k0 = 0; k0 < K; k0 += BK) {
        float4 a4 = *(const float4*)(Ab + (size_t)lr * K + k0 + lc);
        float4 b4 = *(const float4*)(Wb + (size_t)lr * K + k0 + lc);
        As[lc + 0][lr] = a4.x; As[lc + 1][lr] = a4.y;
        As[lc + 2][lr] = a4.z; As[lc + 3][lr] = a4.w;
        Bs[lc + 0][lr] = b4.x; Bs[lc + 1][lr] = b4.y;
        Bs[lc + 2][lr] = b4.z; Bs[lc + 3][lr] = b4.w;
        __syncthreads();

        #pragma unroll
        for (int k = 0; k < BK; k++) {
            float4 ra0 = *(const float4*)&As[k][ty * 8];
            float4 ra1 = *(const float4*)&As[k][ty * 8 + 4];
            float4 rb0 = *(const float4*)&Bs[k][tx * 8];
            float4 rb1 = *(const float4*)&Bs[k][tx * 8 + 4];
            float ra[8] = {ra0.x, ra0.y, ra0.z, ra0.w, ra1.x, ra1.y, ra1.z, ra1.w};
            float rb[8] = {rb0.x, rb0.y, rb0.z, rb0.w, rb1.x, rb1.y, rb1.z, rb1.w};
            #pragma unroll
            for (int i = 0; i < 8; i++)
                #pragma unroll
                for (int j = 0; j < 8; j++)
                    acc[i][j] = fmaf(ra[i], rb[j], acc[i][j]);
        }
        __syncthreads();
    }

    const int cn = bx * BN + tx * 8;
    float4 bi0 = *(const float4*)&bias[cn];
    float4 bi1 = *(const float4*)&bias[cn + 4];
    #pragma unroll
    for (int i = 0; i < 8; i++) {
        size_t r = (size_t)(by * BM + ty * 8 + i);
        float4 o0 = {acc[i][0] + bi0.x, acc[i][1] + bi0.y,
                     acc[i][2] + bi0.z, acc[i][3] + bi0.w};
        float4 o1 = {acc[i][4] + bi1.x, acc[i][5] + bi1.y,
                     acc[i][6] + bi1.z, acc[i][7] + bi1.w};
        *(float4*)&C[r * N + cn]     = o0;
        *(float4*)&C[r * N + cn + 4] = o1;
    }
}

// ---------------- fused gate + sequential scan -----------------------------
// h_t = (sig(f)*h_{t-1} + sig(i)*h_tilde) / (sig(f)+sig(i)); out -> g_bufA
__global__ void scan_k(const float* __restrict__ F, const float* __restrict__ I,
                       const float* __restrict__ Ht, float* __restrict__ Out)
{
    int t = blockIdx.x * blockDim.x + threadIdx.x;
    if (t >= Bx * Hx) return;
    int b = t >> 10;          // / Hx
    int h = t & (Hx - 1);
    size_t base = (size_t)b * Sx * Hx + h;
    float hp = 0.f;
    #pragma unroll 4
    for (int s = 0; s < Sx; s++) {
        size_t idx = base + (size_t)s * Hx;
        float fpre = F[idx], ipre = I[idx], hv = Ht[idx];
        float f = 1.f / (1.f + __expf(-fpre));
        float i = 1.f / (1.f + __expf(-ipre));
        float r = 1.f / (f + i);
        hp = (f * hp + i * hv) * r;
        Out[idx] = hp;
    }
}

// ---------------- small vec-mat: out[b,n] = dot(X[b,:], W[n,:]) + bias -----
// One warp per output element. K fixed at 1024. Optional residual add.
__global__ void vecmat_k(const float* __restrict__ X, int xStride,
                         const float* __restrict__ W, const float* __restrict__ bias,
                         const float* __restrict__ res, int resStride,
                         float* __restrict__ out, int Bn, int N)
{
    int gw = (blockIdx.x * blockDim.x + threadIdx.x) >> 5;
    int lane = threadIdx.x & 31;
    if (gw >= Bn * N) return;
    int b = gw / N, n = gw % N;
    const float* xr = X + (size_t)b * xStride;
    const float* wr = W + (size_t)n * Hx;
    float s = 0.f;
    #pragma unroll
    for (int k = lane * 4; k < Hx; k += 128) {
        float4 xv = *(const float4*)(xr + k);
        float4 wv = *(const float4*)(wr + k);
        s += xv.x * wv.x + xv.y * wv.y + xv.z * wv.z + xv.w * wv.w;
    }
    #pragma unroll
    for (int o = 16; o; o >>= 1) s += __shfl_xor_sync(0xffffffffu, s, o);
    if (lane == 0) {
        float v = s + bias[n];
        if (res) v += res[(size_t)b * resStride + n];
        out[(size_t)b * N + n] = v;
    }
}

// ---------------- attention scores for the LAST query row only -------------
__global__ void scores_k(const float* __restrict__ q, const float* __restrict__ Kb,
                         float* __restrict__ sc)
{
    int gw = (blockIdx.x * blockDim.x + threadIdx.x) >> 5;
    int lane = threadIdx.x & 31;
    if (gw >= Bx * NHx * Sx) return;
    int j = gw & (Sx - 1);
    int bh = gw >> 10;
    int head = bh & (NHx - 1);
    int b = bh >> 3;
    const float4* qr = (const float4*)(q + (size_t)b * Hx + head * DHx);
    const float4* kr = (const float4*)(Kb + ((size_t)b * Sx + j) * Hx + head * DHx);
    float4 qv = qr[lane], kv = kr[lane];
    float s = qv.x * kv.x + qv.y * kv.y + qv.z * kv.z + qv.w * kv.w;
    #pragma unroll
    for (int o = 16; o; o >>= 1) s += __shfl_xor_sync(0xffffffffu, s, o);
    if (lane == 0) sc[(size_t)bh * Sx + j] = s * 0.0883883476483184f; // 1/sqrt(128)
}

// ---------------- softmax over S per (b,head) ------------------------------
__global__ __launch_bounds__(256) void softmax_k(float* __restrict__ sc)
{
    int row = blockIdx.x;
    float4* p = (float4*)(sc + (size_t)row * Sx);
    int t = threadIdx.x;
    float4 v = p[t];
    __shared__ float sh[8];

    float m = fmaxf(fmaxf(v.x, v.y), fmaxf(v.z, v.w));
    #pragma unroll
    for (int o = 16; o; o >>= 1) m = fmaxf(m, __shfl_xor_sync(0xffffffffu, m, o));
    if ((t & 31) == 0) sh[t >> 5] = m;
    __syncthreads();
    m = sh[0];
    #pragma unroll
    for (int i = 1; i < 8; i++) m = fmaxf(m, sh[i]);

    v.x = __expf(v.x - m); v.y = __expf(v.y - m);
    v.z = __expf(v.z - m); v.w = __expf(v.w - m);
    float sum = v.x + v.y + v.z + v.w;
    #pragma unroll
    for (int o = 16; o; o >>= 1) sum += __shfl_xor_sync(0xffffffffu, sum, o);
    __syncthreads();
    if ((t & 31) == 0) sh[t >> 5] = sum;
    __syncthreads();
    sum = 0.f;
    #pragma unroll
    for (int i = 0; i < 8; i++) sum += sh[i];
    float inv = 1.f / sum;
    v.x *= inv; v.y *= inv; v.z *= inv; v.w *= inv;
    p[t] = v;
}

// ---------------- attn @ V for last query row ------------------------------
__global__ __launch_bounds__(128) void av_k(const float* __restrict__ sc,
                                            const float* __restrict__ V,
                                            float* __restrict__ o)
{
    int bh = blockIdx.x;
    int head = bh & (NHx - 1);
    int b = bh >> 3;
    int c = threadIdx.x;   // 0..127
    const float* vp = V + (size_t)b * Sx * Hx + (size_t)head * DHx + c;
    const float* ap = sc + (size_t)bh * Sx;
    float a0 = 0.f, a1 = 0.f, a2 = 0.f, a3 = 0.f;
    #pragma unroll 2
    for (int j = 0; j < Sx; j += 4) {
        a0 = fmaf(ap[j + 0], vp[(size_t)(j + 0) * Hx], a0);
        a1 = fmaf(ap[j + 1], vp[(size_t)(j + 1) * Hx], a1);
        a2 = fmaf(ap[j + 2], vp[(size_t)(j + 2) * Hx], a2);
        a3 = fmaf(ap[j + 3], vp[(size_t)(j + 3) * Hx], a3);
    }
    o[(size_t)b * Hx + head * DHx + c] = (a0 + a1) + (a2 + a3);
}

// ---------------- launch orchestration -------------------------------------
extern "C" void kernel_launch(void* const* d_in, const int* in_sizes, int n_in,
                              void* d_out, int out_size)
{
    const float* x    = (const float*)d_in[0];
    const float* Wf   = (const float*)d_in[1];
    const float* bf   = (const float*)d_in[2];
    const float* Wi   = (const float*)d_in[3];
    const float* bi   = (const float*)d_in[4];
    const float* Wh   = (const float*)d_in[5];
    const float* bh   = (const float*)d_in[6];
    const float* inw  = (const float*)d_in[7];
    const float* inb  = (const float*)d_in[8];
    const float* outw = (const float*)d_in[9];
    const float* outb = (const float*)d_in[10];
    const float* fcw  = (const float*)d_in[11];
    const float* fcb  = (const float*)d_in[12];
    float* out = (float*)d_out;

    float *bufA, *bufF, *bufI, *bufH, *scoresP, *qP, *oP, *lastP;
    cudaGetSymbolAddress((void**)&bufA, g_bufA);
    cudaGetSymbolAddress((void**)&bufF, g_bufF);
    cudaGetSymbolAddress((void**)&bufI, g_bufI);
    cudaGetSymbolAddress((void**)&bufH, g_bufH);
    cudaGetSymbolAddress((void**)&scoresP, g_scores);
    cudaGetSymbolAddress((void**)&qP, g_q);
    cudaGetSymbolAddress((void**)&oP, g_o);
    cudaGetSymbolAddress((void**)&lastP, g_last);

    dim3 gg(Hx / BN, Mx / BM);   // (8, 128)

    // 4 minLSTM layers
    for (int l = 0; l < Lx; l++) {
        const float* in = (l == 0) ? x : bufA;
        size_t wo = (size_t)l * Hx * Hx;
        sgemm_k<<<gg, 256>>>(in, Wf + wo, bf + (size_t)l * Hx, bufF);
        sgemm_k<<<gg, 256>>>(in, Wi + wo, bi + (size_t)l * Hx, bufI);
        sgemm_k<<<gg, 256>>>(in, Wh + wo, bh + (size_t)l * Hx, bufH);
        scan_k<<<(Bx * Hx) / 256, 256>>>(bufF, bufI, bufH, bufA);
    }

    // Attention: full K,V projections; only the LAST query row matters.
    sgemm_k<<<gg, 256>>>(bufA, inw + (size_t)Hx * Hx,     inb + Hx,     bufF); // K
    sgemm_k<<<gg, 256>>>(bufA, inw + (size_t)2 * Hx * Hx, inb + 2 * Hx, bufI); // V

    // q at position S-1: [B, H]
    vecmat_k<<<(Bx * Hx * 32 + 255) / 256, 256>>>(
        bufA + (size_t)(Sx - 1) * Hx, Sx * Hx, inw, inb, nullptr, 0, qP, Bx, Hx);

    scores_k<<<(Bx * NHx * Sx * 32) / 256, 256>>>(qP, bufF, scoresP);
    softmax_k<<<Bx * NHx, 256>>>(scoresP);
    av_k<<<Bx * NHx, 128>>>(scoresP, bufI, oP);

    // out-proj + residual (last token), then fc head -> d_out [B, O]
    vecmat_k<<<(Bx * Hx * 32 + 255) / 256, 256>>>(
        oP, Hx, outw, outb, bufA + (size_t)(Sx - 1) * Hx, Sx * Hx, lastP, Bx, Hx);
    vecmat_k<<<(Bx * Ox * 32 + 255) / 256, 256>>>(
        lastP, Hx, fcw, fcb, nullptr, 0, out, Bx, Ox);
}

// round 2
// speedup vs baseline: 1.3691x; 1.3691x over previous
#include <cuda_runtime.h>
#include <math.h>

// Problem constants
#define Bx  16
#define Sx  1024
#define Hx  1024
#define Ox  256
#define Lx  4
#define NHx 8
#define DHx 128
#define Mx  (Bx*Sx)   // 16384 rows
#define CT  32        // scan chunk length
#define CC  (Sx/CT)   // 32 chunks

typedef unsigned long long u64;

// ---------------- scratch (device globals: no allocation allowed) ----------
__device__ float g_bufA[(size_t)Mx * Hx];   // activations (layer in/out)
__device__ float g_bufF[(size_t)Mx * Hx];   // f preact -> p ; later K
__device__ float g_bufI[(size_t)Mx * Hx];   // i preact -> q ; later V
__device__ float g_bufH[(size_t)Mx * Hx];   // h_tilde preact
__device__ float g_chP[Bx * Hx * CC];
__device__ float g_chQ[Bx * Hx * CC];
__device__ float g_chS[Bx * Hx * CC];
__device__ float g_scores[Bx * NHx * Sx];
__device__ float g_q[Bx * Hx];
__device__ float g_o[Bx * Hx];
__device__ float g_last[Bx * Hx];

// ---------------- packed f32x2 helpers -------------------------------------
__device__ __forceinline__ u64 dup_f32x2(float x) {
    u64 r; asm("mov.b64 %0, {%1, %1};" : "=l"(r) : "f"(x)); return r;
}
__device__ __forceinline__ void ffma2(u64 &acc, u64 a, u64 b) {
    asm("fma.rn.f32x2 %0, %1, %2, %0;" : "+l"(acc) : "l"(a), "l"(b));
}
__device__ __forceinline__ float2 unpack_f32x2(u64 v) {
    float2 r; asm("mov.b64 {%0, %1}, %2;" : "=f"(r.x), "=f"(r.y) : "l"(v)); return r;
}
__device__ __forceinline__ float fast_rcp(float x) {
    float r; asm("rcp.approx.f32 %0, %1;" : "=f"(r) : "f"(x)); return r;
}

// ---------------- SGEMM: C[M,N] = A[M,K] * W[N,K]^T + bias[N] --------------
// M=16384, N=K=1024 fixed. 128x128 tile, BK=8, 256 threads, 8x8 per thread,
// accumulators packed as f32x2 pairs along N -> FFMA2.
#define BM 128
#define BN 128
#define BK 8

__global__ __launch_bounds__(256) void sgemm_k(
    const float* __restrict__ A, const float* __restrict__ W,
    const float* __restrict__ bias, float* __restrict__ C)
{
    __shared__ float As[BK][BM];
    __shared__ float Bs[BK][BN];

    const int tid = threadIdx.x;
    const int bx = blockIdx.x;   // N tile
    const int by = blockIdx.y;   // M tile
    const int K = Hx, N = Hx;

    const float* Ab = A + (size_t)by * BM * K;
    const float* Wb = W + (size_t)bx * BN * K;

    const int lr = tid >> 1;          // 0..127 row within tile
    const int lc = (tid & 1) * 4;     // 0 or 4 within BK
    const int ty = tid >> 4;          // 0..15 -> row group
    const int tx = tid & 15;          // 0..15 -> col group

    u64 acc2[8][4];
    #pragma unroll
    for (int i = 0; i < 8; i++)
        #pragma unroll
        for (int j = 0; j < 4; j++)
            acc2[i][j] = 0ull;

    // prefetch first tile
    float4 a4 = *(const float4*)(Ab + (size_t)lr * K + lc);
    float4 b4 = *(const float4*)(Wb + (size_t)lr * K + lc);

    for (int k0 = 0; k0 < K; k0 += BK) {
        As[lc + 0][lr] = a4.x; As[lc + 1][lr] = a4.y;
        As[lc + 2][lr] = a4.z; As[lc + 3][lr] = a4.w;
        Bs[lc + 0][lr] = b4.x; Bs[lc + 1][lr] = b4.y;
        Bs[lc + 2][lr] = b4.z; Bs[lc + 3][lr] = b4.w;
        __syncthreads();

        if (k0 + BK < K) {
            a4 = *(const float4*)(Ab + (size_t)lr * K + k0 + BK + lc);
            b4 = *(const float4*)(Wb + (size_t)lr * K + k0 + BK + lc);
        }

        #pragma unroll
        for (int k = 0; k < BK; k++) {
            float4 ra0 = *(const float4*)&As[k][ty * 8];
            float4 ra1 = *(const float4*)&As[k][ty * 8 + 4];
            u64 rb[4];
            rb[0] = *(const u64*)&Bs[k][tx * 8 + 0];
            rb[1] = *(const u64*)&Bs[k][tx * 8 + 2];
            rb[2] = *(const u64*)&Bs[k][tx * 8 + 4];
            rb[3] = *(const u64*)&Bs[k][tx * 8 + 6];
            float ra[8] = {ra0.x, ra0.y, ra0.z, ra0.w, ra1.x, ra1.y, ra1.z, ra1.w};
            #pragma unroll
            for (int i = 0; i < 8; i++) {
                u64 a2 = dup_f32x2(ra[i]);
                ffma2(acc2[i][0], a2, rb[0]);
                ffma2(acc2[i][1], a2, rb[1]);
                ffma2(acc2[i][2], a2, rb[2]);
                ffma2(acc2[i][3], a2, rb[3]);
            }
        }
        __syncthreads();
    }

    const int cn = bx * BN + tx * 8;
    float4 bi0 = *(const float4*)&bias[cn];
    float4 bi1 = *(const float4*)&bias[cn + 4];
    #pragma unroll
    for (int i = 0; i < 8; i++) {
        size_t r = (size_t)(by * BM + ty * 8 + i);
        float2 p0 = unpack_f32x2(acc2[i][0]);
        float2 p1 = unpack_f32x2(acc2[i][1]);
        float2 p2 = unpack_f32x2(acc2[i][2]);
        float2 p3 = unpack_f32x2(acc2[i][3]);
        float4 o0 = {p0.x + bi0.x, p0.y + bi0.y, p1.x + bi0.z, p1.y + bi0.w};
        float4 o1 = {p2.x + bi1.x, p2.y + bi1.y, p3.x + bi1.z, p3.y + bi1.w};
        *(float4*)&C[r * N + cn]     = o0;
        *(float4*)&C[r * N + cn + 4] = o1;
    }
}

// ---------------- chunked minLSTM scan -------------------------------------
// recurrence: h_t = p_t*h_{t-1} + q_t
//   p = e^f(1+e^i)*r,  q = e^i(1+e^f)*h~*r,  r = 1/(e^f(1+e^i)+e^i(1+e^f))
// pass1: compute p,q per element (overwrite F,I), compose per chunk -> chP,chQ
__global__ __launch_bounds__(256) void scan_p1(
    const float* __restrict__ F, const float* __restrict__ I,
    const float* __restrict__ Ht, float* __restrict__ P, float* __restrict__ Q,
    float* __restrict__ chP, float* __restrict__ chQ)
{
    int t = blockIdx.x * blockDim.x + threadIdx.x;   // < Bx*CC*Hx
    int h = t & (Hx - 1);
    int bc = t >> 10;
    int c = bc & (CC - 1);
    int b = bc >> 5;
    size_t base = ((size_t)b * Sx + (size_t)c * CT) * Hx + h;
    float accP = 1.f, accQ = 0.f;
    #pragma unroll 4
    for (int s = 0; s < CT; s++) {
        size_t idx = base + (size_t)s * Hx;
        float ea = __expf(F[idx]);
        float eb = __expf(I[idx]);
        float hv = Ht[idx];
        float na = ea * (1.f + eb);
        float nb = eb * (1.f + ea);
        float r = fast_rcp(na + nb);
        float p = na * r;
        float q = nb * r * hv;
        P[idx] = p; Q[idx] = q;
        accQ = fmaf(p, accQ, q);
        accP *= p;
    }
    chP[t] = accP;
    chQ[t] = accQ;
}

// pass2: prefix over chunks per (b,h); chS[c] = h entering chunk c
__global__ __launch_bounds__(256) void scan_p2(
    const float* __restrict__ chP, const float* __restrict__ chQ,
    float* __restrict__ chS)
{
    int u = blockIdx.x * blockDim.x + threadIdx.x;   // < Bx*Hx
    int h = u & (Hx - 1);
    int b = u >> 10;
    float hc = 0.f;
    #pragma unroll
    for (int c = 0; c < CC; c++) {
        size_t idx = ((size_t)b * CC + c) * Hx + h;
        chS[idx] = hc;
        hc = fmaf(chP[idx], hc, chQ[idx]);
    }
}

// pass3: apply scan with correct chunk-start values
__global__ __launch_bounds__(256) void scan_p3(
    const float* __restrict__ P, const float* __restrict__ Q,
    const float* __restrict__ chS, float* __restrict__ Out)
{
    int t = blockIdx.x * blockDim.x + threadIdx.x;
    int h = t & (Hx - 1);
    int bc = t >> 10;
    int c = bc & (CC - 1);
    int b = bc >> 5;
    size_t base = ((size_t)b * Sx + (size_t)c * CT) * Hx + h;
    float hp = chS[t];
    #pragma unroll 4
    for (int s = 0; s < CT; s++) {
        size_t idx = base + (size_t)s * Hx;
        hp = fmaf(P[idx], hp, Q[idx]);
        Out[idx] = hp;
    }
}

// ---------------- small vec-mat: out[b,n] = dot(X[b,:], W[n,:]) + bias -----
__global__ void vecmat_k(const float* __restrict__ X, int xStride,
                         const float* __restrict__ W, const float* __restrict__ bias,
                         const float* __restrict__ res, int resStride,
                         float* __restrict__ out, int Bn, int N)
{
    int gw = (blockIdx.x * blockDim.x + threadIdx.x) >> 5;
    int lane = threadIdx.x & 31;
    if (gw >= Bn * N) return;
    int b = gw / N, n = gw % N;
    const float* xr = X + (size_t)b * xStride;
    const float* wr = W + (size_t)n * Hx;
    float s = 0.f;
    #pragma unroll
    for (int k = lane * 4; k < Hx; k += 128) {
        float4 xv = *(const float4*)(xr + k);
        float4 wv = *(const float4*)(wr + k);
        s += xv.x * wv.x + xv.y * wv.y + xv.z * wv.z + xv.w * wv.w;
    }
    #pragma unroll
    for (int o = 16; o; o >>= 1) s += __shfl_xor_sync(0xffffffffu, s, o);
    if (lane == 0) {
        float v = s + bias[n];
        if (res) v += res[(size_t)b * resStride + n];
        out[(size_t)b * N + n] = v;
    }
}

// ---------------- attention scores for the LAST query row only -------------
__global__ void scores_k(const float* __restrict__ q, const float* __restrict__ Kb,
                         float* __restrict__ sc)
{
    int gw = (blockIdx.x * blockDim.x + threadIdx.x) >> 5;
    int lane = threadIdx.x & 31;
    if (gw >= Bx * NHx * Sx) return;
    int j = gw & (Sx - 1);
    int bh = gw >> 10;
    int head = bh & (NHx - 1);
    int b = bh >> 3;
    const float4* qr = (const float4*)(q + (size_t)b * Hx + head * DHx);
    const float4* kr = (const float4*)(Kb + ((size_t)b * Sx + j) * Hx + head * DHx);
    float4 qv = qr[lane], kv = kr[lane];
    float s = qv.x * kv.x + qv.y * kv.y + qv.z * kv.z + qv.w * kv.w;
    #pragma unroll
    for (int o = 16; o; o >>= 1) s += __shfl_xor_sync(0xffffffffu, s, o);
    if (lane == 0) sc[(size_t)bh * Sx + j] = s * 0.0883883476483184f; // 1/sqrt(128)
}

// ---------------- softmax over S per (b,head) ------------------------------
__global__ __launch_bounds__(256) void softmax_k(float* __restrict__ sc)
{
    int row = blockIdx.x;
    float4* p = (float4*)(sc + (size_t)row * Sx);
    int t = threadIdx.x;
    float4 v = p[t];
    __shared__ float sh[8];

    float m = fmaxf(fmaxf(v.x, v.y), fmaxf(v.z, v.w));
    #pragma unroll
    for (int o = 16; o; o >>= 1) m = fmaxf(m, __shfl_xor_sync(0xffffffffu, m, o));
    if ((t & 31) == 0) sh[t >> 5] = m;
    __syncthreads();
    m = sh[0];
    #pragma unroll
    for (int i = 1; i < 8; i++) m = fmaxf(m, sh[i]);

    v.x = __expf(v.x - m); v.y = __expf(v.y - m);
    v.z = __expf(v.z - m); v.w = __expf(v.w - m);
    float sum = v.x + v.y + v.z + v.w;
    #pragma unroll
    for (int o = 16; o; o >>= 1) sum += __shfl_xor_sync(0xffffffffu, sum, o);
    __syncthreads();
    if ((t & 31) == 0) sh[t >> 5] = sum;
    __syncthreads();
    sum = 0.f;
    #pragma unroll
    for (int i = 0; i < 8; i++) sum += sh[i];
    float inv = 1.f / sum;
    v.x *= inv; v.y *= inv; v.z *= inv; v.w *= inv;
    p[t] = v;
}

// ---------------- attn @ V for last query row ------------------------------
__global__ __launch_bounds__(128) void av_k(const float* __restrict__ sc,
                                            const float* __restrict__ V,
                                            float* __restrict__ o)
{
    int bh = blockIdx.x;
    int head = bh & (NHx - 1);
    int b = bh >> 3;
    int c = threadIdx.x;   // 0..127
    const float* vp = V + (size_t)b * Sx * Hx + (size_t)head * DHx + c;
    const float* ap = sc + (size_t)bh * Sx;
    float a0 = 0.f, a1 = 0.f, a2 = 0.f, a3 = 0.f;
    #pragma unroll 2
    for (int j = 0; j < Sx; j += 4) {
        a0 = fmaf(ap[j + 0], vp[(size_t)(j + 0) * Hx], a0);
        a1 = fmaf(ap[j + 1], vp[(size_t)(j + 1) * Hx], a1);
        a2 = fmaf(ap[j + 2], vp[(size_t)(j + 2) * Hx], a2);
        a3 = fmaf(ap[j + 3], vp[(size_t)(j + 3) * Hx], a3);
    }
    o[(size_t)b * Hx + head * DHx + c] = (a0 + a1) + (a2 + a3);
}

// ---------------- launch orchestration -------------------------------------
extern "C" void kernel_launch(void* const* d_in, const int* in_sizes, int n_in,
                              void* d_out, int out_size)
{
    const float* x    = (const float*)d_in[0];
    const float* Wf   = (const float*)d_in[1];
    const float* bf   = (const float*)d_in[2];
    const float* Wi   = (const float*)d_in[3];
    const float* bi   = (const float*)d_in[4];
    const float* Wh   = (const float*)d_in[5];
    const float* bh   = (const float*)d_in[6];
    const float* inw  = (const float*)d_in[7];
    const float* inb  = (const float*)d_in[8];
    const float* outw = (const float*)d_in[9];
    const float* outb = (const float*)d_in[10];
    const float* fcw  = (const float*)d_in[11];
    const float* fcb  = (const float*)d_in[12];
    float* out = (float*)d_out;

    float *bufA, *bufF, *bufI, *bufH, *chP, *chQ, *chS;
    float *scoresP, *qP, *oP, *lastP;
    cudaGetSymbolAddress((void**)&bufA, g_bufA);
    cudaGetSymbolAddress((void**)&bufF, g_bufF);
    cudaGetSymbolAddress((void**)&bufI, g_bufI);
    cudaGetSymbolAddress((void**)&bufH, g_bufH);
    cudaGetSymbolAddress((void**)&chP, g_chP);
    cudaGetSymbolAddress((void**)&chQ, g_chQ);
    cudaGetSymbolAddress((void**)&chS, g_chS);
    cudaGetSymbolAddress((void**)&scoresP, g_scores);
    cudaGetSymbolAddress((void**)&qP, g_q);
    cudaGetSymbolAddress((void**)&oP, g_o);
    cudaGetSymbolAddress((void**)&lastP, g_last);

    dim3 gg(Hx / BN, Mx / BM);   // (8, 128)
    const int scanT = Bx * CC * Hx;   // 512K threads

    // 4 minLSTM layers
    for (int l = 0; l < Lx; l++) {
        const float* in = (l == 0) ? x : bufA;
        size_t wo = (size_t)l * Hx * Hx;
        sgemm_k<<<gg, 256>>>(in, Wf + wo, bf + (size_t)l * Hx, bufF);
        sgemm_k<<<gg, 256>>>(in, Wi + wo, bi + (size_t)l * Hx, bufI);
        sgemm_k<<<gg, 256>>>(in, Wh + wo, bh + (size_t)l * Hx, bufH);
        scan_p1<<<scanT / 256, 256>>>(bufF, bufI, bufH, bufF, bufI, chP, chQ);
        scan_p2<<<(Bx * Hx) / 256, 256>>>(chP, chQ, chS);
        scan_p3<<<scanT / 256, 256>>>(bufF, bufI, chS, bufA);
    }

    // Attention: full K,V projections; only the LAST query row matters.
    sgemm_k<<<gg, 256>>>(bufA, inw + (size_t)Hx * Hx,     inb + Hx,     bufF); // K
    sgemm_k<<<gg, 256>>>(bufA, inw + (size_t)2 * Hx * Hx, inb + 2 * Hx, bufI); // V

    // q at position S-1: [B, H]
    vecmat_k<<<(Bx * Hx * 32 + 255) / 256, 256>>>(
        bufA + (size_t)(Sx - 1) * Hx, Sx * Hx, inw, inb, nullptr, 0, qP, Bx, Hx);

    scores_k<<<(Bx * NHx * Sx * 32) / 256, 256>>>(qP, bufF, scoresP);
    softmax_k<<<Bx * NHx, 256>>>(scoresP);
    av_k<<<Bx * NHx, 128>>>(scoresP, bufI, oP);

    // out-proj + residual (last token), then fc head -> d_out [B, O]
    vecmat_k<<<(Bx * Hx * 32 + 255) / 256, 256>>>(
        oP, Hx, outw, outb, bufA + (size_t)(Sx - 1) * Hx, Sx * Hx, lastP, Bx, Hx);
    vecmat_k<<<(Bx * Ox * 32 + 255) / 256, 256>>>(
        lastP, Hx, fcw, fcb, nullptr, 0, out, Bx, Ox);
}

// round 4
// speedup vs baseline: 2.0847x; 1.5227x over previous
#include <cuda_runtime.h>
#include <cuda_fp16.h>
#include <math.h>
#include <stdint.h>

// Problem constants
#define Bx  16
#define Sx  1024
#define Hx  1024
#define Ox  256
#define Lx  4
#define NHx 8
#define DHx 128
#define Mx  (Bx*Sx)   // 16384 rows
#define CT  32        // scan chunk length
#define CC  (Sx/CT)   // 32 chunks

typedef unsigned long long u64;

// ---------------- scratch (device globals: no allocation allowed) ----------
__device__ float g_bufA[(size_t)Mx * Hx];
__device__ float g_bufF[(size_t)Mx * Hx];
__device__ float g_bufI[(size_t)Mx * Hx];
__device__ float g_bufH[(size_t)Mx * Hx];
__device__ float g_chP[Bx * Hx * CC];
__device__ float g_chQ[Bx * Hx * CC];
__device__ float g_chS[Bx * Hx * CC];
__device__ float g_scores[Bx * NHx * Sx];
__device__ float g_q[Bx * Hx];
__device__ float g_o[Bx * Hx];
__device__ float g_last[Bx * Hx];

// fp16 hi/lo split buffers
#define NWF 4194304          // Wf total elems (4 layers)
#define NWKV 2097152         // K+V proj rows
#define NWTOT (3*NWF + NWKV) // 14680064
__device__ __half g_WH[NWTOT];
__device__ __half g_WL[NWTOT];
__device__ __half g_AH[(size_t)Mx * Hx];
__device__ __half g_AL[(size_t)Mx * Hx];

// ======================= helpers ===========================================
__device__ __forceinline__ uint32_t smem_u32(const void* p) {
    uint32_t a;
    asm("{ .reg .u64 t; cvta.to.shared.u64 t, %1; cvt.u32.u64 %0, t; }"
        : "=r"(a) : "l"(p));
    return a;
}
__device__ __forceinline__ void cpa16(uint32_t dst, const void* src) {
    asm volatile("cp.async.cg.shared.global [%0], [%1], 16;" :: "r"(dst), "l"(src));
}
__device__ __forceinline__ void ldm4(uint32_t& r0, uint32_t& r1,
                                     uint32_t& r2, uint32_t& r3, uint32_t a) {
    asm volatile("ldmatrix.sync.aligned.m8n8.x4.shared.b16 {%0,%1,%2,%3}, [%4];"
        : "=r"(r0), "=r"(r1), "=r"(r2), "=r"(r3) : "r"(a));
}
__device__ __forceinline__ void mma16816(float* d, const uint32_t* a, const uint32_t* b) {
    asm volatile("mma.sync.aligned.m16n8k16.row.col.f32.f16.f16.f32 "
        "{%0,%1,%2,%3}, {%4,%5,%6,%7}, {%8,%9}, {%0,%1,%2,%3};"
        : "+f"(d[0]), "+f"(d[1]), "+f"(d[2]), "+f"(d[3])
        : "r"(a[0]), "r"(a[1]), "r"(a[2]), "r"(a[3]), "r"(b[0]), "r"(b[1]));
}
__device__ __forceinline__ float fast_rcp(float x) {
    float r; asm("rcp.approx.f32 %0, %1;" : "=f"(r) : "f"(x)); return r;
}

// ======================= HGEMM (3x f16 emulated fp32) ======================
// C[M,N] = A[M,K]*W[N,K]^T + bias.  M=16384, N=K=1024.
// CTA tile 128x128, K-chunk 32, 8 warps (warp tile 32x64), 3-stage cp.async.
#define STG_SZ 32768
#define T_AH 0
#define T_AL 8192
#define T_BH 16384
#define T_BL 24576
#define SMEMB (3 * STG_SZ)

__global__ __launch_bounds__(256) void hgemm_k(
    const __half* __restrict__ AH, const __half* __restrict__ AL,
    const __half* __restrict__ WH, const __half* __restrict__ WL,
    const float* __restrict__ bias, float* __restrict__ C)
{
    extern __shared__ __align__(1024) char smem[];
    const uint32_t sb = smem_u32(smem);
    const int tid = threadIdx.x;
    const int wid = tid >> 5, lane = tid & 31;
    const int bx = blockIdx.x, by = blockIdx.y;

    // ---- cp.async lane mapping: row lm, two 16B chunks
    const int lm  = tid >> 1;
    const int lc0 = (tid & 1) * 2;
    const size_t aoff = (size_t)(by * 128 + lm) * Hx;
    const size_t boff = (size_t)(bx * 128 + lm) * Hx;
    const int sws = (lm >> 1) & 3;
    const uint32_t d0 = lm * 64 + 16 * (lc0 ^ sws);
    const uint32_t d1 = lm * 64 + 16 * ((lc0 + 1) ^ sws);
    const int g0 = 8 * lc0, g1 = 8 * (lc0 + 1);

    #define LOAD_CHUNK(k0, s) do {                                          \
        uint32_t st_ = sb + (s) * STG_SZ;                                   \
        cpa16(st_ + T_AH + d0, AH + aoff + (k0) + g0);                      \
        cpa16(st_ + T_AH + d1, AH + aoff + (k0) + g1);                      \
        cpa16(st_ + T_AL + d0, AL + aoff + (k0) + g0);                      \
        cpa16(st_ + T_AL + d1, AL + aoff + (k0) + g1);                      \
        cpa16(st_ + T_BH + d0, WH + boff + (k0) + g0);                      \
        cpa16(st_ + T_BH + d1, WH + boff + (k0) + g1);                      \
        cpa16(st_ + T_BL + d0, WL + boff + (k0) + g0);                      \
        cpa16(st_ + T_BL + d1, WL + boff + (k0) + g1);                      \
        asm volatile("cp.async.commit_group;" ::: "memory");                \
    } while (0)

    // ---- mma lane geometry
    const int wm = (wid & 3) * 32;
    const int wn = (wid >> 2) * 64;
    const int ar0 = wm + (lane & 15);        // A rows for mt=0 (mt=1: +16)
    const int aK  = (lane >> 4) & 1;         // +8 in k
    const int bK  = (lane >> 3) & 1;
    const int bnh = (lane >> 4) & 1;         // n-tile within pair
    const int br0 = wn + (lane & 7);

    float acc[2][8][4];
    #pragma unroll
    for (int i = 0; i < 2; i++)
        #pragma unroll
        for (int j = 0; j < 8; j++)
            #pragma unroll
            for (int q = 0; q < 4; q++)
                acc[i][j][q] = 0.f;

    LOAD_CHUNK(0, 0);
    LOAD_CHUNK(32, 1);

    for (int c = 0; c < 32; c++) {
        const int s = c % 3;
        if (c < 31) asm volatile("cp.async.wait_group 1;" ::: "memory");
        else        asm volatile("cp.async.wait_group 0;" ::: "memory");
        __syncthreads();
        if (c + 2 < 32) LOAD_CHUNK((c + 2) * 32, (c + 2) % 3);

        const uint32_t st = sb + s * STG_SZ;
        #pragma unroll
        for (int kk = 0; kk < 2; kk++) {
            uint32_t ah[2][4], al[2][4], bh[8][2], bl[8][2];
            #pragma unroll
            for (int mt = 0; mt < 2; mt++) {
                const int row = ar0 + mt * 16;
                const uint32_t off = (uint32_t)(row * 64
                                   + 16 * ((kk * 2 + aK) ^ ((row >> 1) & 3)));
                ldm4(ah[mt][0], ah[mt][1], ah[mt][2], ah[mt][3], st + T_AH + off);
                ldm4(al[mt][0], al[mt][1], al[mt][2], al[mt][3], st + T_AL + off);
            }
            #pragma unroll
            for (int p = 0; p < 4; p++) {
                const int row = br0 + (p * 2 + bnh) * 8;
                const uint32_t off = (uint32_t)(row * 64
                                   + 16 * ((kk * 2 + bK) ^ ((row >> 1) & 3)));
                ldm4(bh[2*p][0], bh[2*p][1], bh[2*p+1][0], bh[2*p+1][1], st + T_BH + off);
                ldm4(bl[2*p][0], bl[2*p][1], bl[2*p+1][0], bl[2*p+1][1], st + T_BL + off);
            }
            // product 1: hi*hi
            #pragma unroll
            for (int mt = 0; mt < 2; mt++)
                #pragma unroll
                for (int nt = 0; nt < 8; nt++)
                    mma16816(acc[mt][nt], ah[mt], bh[nt]);
            // product 2: hi*lo
            #pragma unroll
            for (int mt = 0; mt < 2; mt++)
                #pragma unroll
                for (int nt = 0; nt < 8; nt++)
                    mma16816(acc[mt][nt], ah[mt], bl[nt]);
            // product 3: lo*hi
            #pragma unroll
            for (int mt = 0; mt < 2; mt++)
                #pragma unroll
                for (int nt = 0; nt < 8; nt++)
                    mma16816(acc[mt][nt], al[mt], bh[nt]);
        }
    }

    // ---- epilogue
    const int r0 = lane >> 2;
    const int cc = (lane & 3) * 2;
    #pragma unroll
    for (int mt = 0; mt < 2; mt++) {
        const int mrow = by * 128 + wm + mt * 16 + r0;
        #pragma unroll
        for (int nt = 0; nt < 8; nt++) {
            const int col = bx * 128 + wn + nt * 8 + cc;
            const float b0 = bias[col], b1 = bias[col + 1];
            float2 v0 = {acc[mt][nt][0] + b0, acc[mt][nt][1] + b1};
            float2 v1 = {acc[mt][nt][2] + b0, acc[mt][nt][3] + b1};
            *(float2*)&C[(size_t)mrow * Hx + col]       = v0;
            *(float2*)&C[(size_t)(mrow + 8) * Hx + col] = v1;
        }
    }
}

// ---------------- fp32 -> f16 hi/lo conversion -----------------------------
__global__ __launch_bounds__(256) void conv_k(
    const float* __restrict__ src, __half* __restrict__ hi,
    __half* __restrict__ lo, int n)
{
    int i = blockIdx.x * blockDim.x + threadIdx.x;
    if (i >= n / 4) return;
    float4 v = ((const float4*)src)[i];
    __half h0 = __float2half_rn(v.x), h1 = __float2half_rn(v.y);
    __half h2 = __float2half_rn(v.z), h3 = __float2half_rn(v.w);
    __half l0 = __float2half_rn(v.x - __half2float(h0));
    __half l1 = __float2half_rn(v.y - __half2float(h1));
    __half l2 = __float2half_rn(v.z - __half2float(h2));
    __half l3 = __float2half_rn(v.w - __half2float(h3));
    __half2* hp = (__half2*)hi;
    __half2* lp = (__half2*)lo;
    hp[i * 2]     = __halves2half2(h0, h1);
    hp[i * 2 + 1] = __halves2half2(h2, h3);
    lp[i * 2]     = __halves2half2(l0, l1);
    lp[i * 2 + 1] = __halves2half2(l2, l3);
}

// ---------------- chunked minLSTM scan -------------------------------------
__global__ __launch_bounds__(256) void scan_p1(
    const float* __restrict__ F, const float* __restrict__ I,
    const float* __restrict__ Ht, float* __restrict__ P, float* __restrict__ Q,
    float* __restrict__ chP, float* __restrict__ chQ)
{
    int t = blockIdx.x * blockDim.x + threadIdx.x;
    int h = t & (Hx - 1);
    int bc = t >> 10;
    int c = bc & (CC - 1);
    int b = bc >> 5;
    size_t base = ((size_t)b * Sx + (size_t)c * CT) * Hx + h;
    float accP = 1.f, accQ = 0.f;
    #pragma unroll 4
    for (int s = 0; s < CT; s++) {
        size_t idx = base + (size_t)s * Hx;
        float ea = __expf(F[idx]);
        float eb = __expf(I[idx]);
        float hv = Ht[idx];
        float na = ea * (1.f + eb);
        float nb = eb * (1.f + ea);
        float r = fast_rcp(na + nb);
        float p = na * r;
        float q = nb * r * hv;
        P[idx] = p; Q[idx] = q;
        accQ = fmaf(p, accQ, q);
        accP *= p;
    }
    chP[t] = accP;
    chQ[t] = accQ;
}

__global__ __launch_bounds__(256) void scan_p2(
    const float* __restrict__ chP, const float* __restrict__ chQ,
    float* __restrict__ chS)
{
    int u = blockIdx.x * blockDim.x + threadIdx.x;
    int h = u & (Hx - 1);
    int b = u >> 10;
    float hc = 0.f;
    #pragma unroll
    for (int c = 0; c < CC; c++) {
        size_t idx = ((size_t)b * CC + c) * Hx + h;
        chS[idx] = hc;
        hc = fmaf(chP[idx], hc, chQ[idx]);
    }
}

// pass3 also emits fp16 hi/lo of the activation for the next GEMM layer
__global__ __launch_bounds__(256) void scan_p3(
    const float* __restrict__ P, const float* __restrict__ Q,
    const float* __restrict__ chS, float* __restrict__ Out,
    __half* __restrict__ OH, __half* __restrict__ OL)
{
    int t = blockIdx.x * blockDim.x + threadIdx.x;
    int h = t & (Hx - 1);
    int bc = t >> 10;
    int c = bc & (CC - 1);
    int b = bc >> 5;
    size_t base = ((size_t)b * Sx + (size_t)c * CT) * Hx + h;
    float hp = chS[t];
    #pragma unroll 4
    for (int s = 0; s < CT; s++) {
        size_t idx = base + (size_t)s * Hx;
        hp = fmaf(P[idx], hp, Q[idx]);
        Out[idx] = hp;
        __half hh = __float2half_rn(hp);
        OH[idx] = hh;
        OL[idx] = __float2half_rn(hp - __half2float(hh));
    }
}

// ---------------- small vec-mat --------------------------------------------
__global__ void vecmat_k(const float* __restrict__ X, int xStride,
                         const float* __restrict__ W, const float* __restrict__ bias,
                         const float* __restrict__ res, int resStride,
                         float* __restrict__ out, int Bn, int N)
{
    int gw = (blockIdx.x * blockDim.x + threadIdx.x) >> 5;
    int lane = threadIdx.x & 31;
    if (gw >= Bn * N) return;
    int b = gw / N, n = gw % N;
    const float* xr = X + (size_t)b * xStride;
    const float* wr = W + (size_t)n * Hx;
    float s = 0.f;
    #pragma unroll
    for (int k = lane * 4; k < Hx; k += 128) {
        float4 xv = *(const float4*)(xr + k);
        float4 wv = *(const float4*)(wr + k);
        s += xv.x * wv.x + xv.y * wv.y + xv.z * wv.z + xv.w * wv.w;
    }
    #pragma unroll
    for (int o = 16; o; o >>= 1) s += __shfl_xor_sync(0xffffffffu, s, o);
    if (lane == 0) {
        float v = s + bias[n];
        if (res) v += res[(size_t)b * resStride + n];
        out[(size_t)b * N + n] = v;
    }
}

// ---------------- attention (last query row only) --------------------------
__global__ void scores_k(const float* __restrict__ q, const float* __restrict__ Kb,
                         float* __restrict__ sc)
{
    int gw = (blockIdx.x * blockDim.x + threadIdx.x) >> 5;
    int lane = threadIdx.x & 31;
    if (gw >= Bx * NHx * Sx) return;
    int j = gw & (Sx - 1);
    int bh = gw >> 10;
    int head = bh & (NHx - 1);
    int b = bh >> 3;
    const float4* qr = (const float4*)(q + (size_t)b * Hx + head * DHx);
    const float4* kr = (const float4*)(Kb + ((size_t)b * Sx + j) * Hx + head * DHx);
    float4 qv = qr[lane], kv = kr[lane];
    float s = qv.x * kv.x + qv.y * kv.y + qv.z * kv.z + qv.w * kv.w;
    #pragma unroll
    for (int o = 16; o; o >>= 1) s += __shfl_xor_sync(0xffffffffu, s, o);
    if (lane == 0) sc[(size_t)bh * Sx + j] = s * 0.0883883476483184f;
}

__global__ __launch_bounds__(256) void softmax_k(float* __restrict__ sc)
{
    int row = blockIdx.x;
    float4* p = (float4*)(sc + (size_t)row * Sx);
    int t = threadIdx.x;
    float4 v = p[t];
    __shared__ float sh[8];

    float m = fmaxf(fmaxf(v.x, v.y), fmaxf(v.z, v.w));
    #pragma unroll
    for (int o = 16; o; o >>= 1) m = fmaxf(m, __shfl_xor_sync(0xffffffffu, m, o));
    if ((t & 31) == 0) sh[t >> 5] = m;
    __syncthreads();
    m = sh[0];
    #pragma unroll
    for (int i = 1; i < 8; i++) m = fmaxf(m, sh[i]);

    v.x = __expf(v.x - m); v.y = __expf(v.y - m);
    v.z = __expf(v.z - m); v.w = __expf(v.w - m);
    float sum = v.x + v.y + v.z + v.w;
    #pragma unroll
    for (int o = 16; o; o >>= 1) sum += __shfl_xor_sync(0xffffffffu, sum, o);
    __syncthreads();
    if ((t & 31) == 0) sh[t >> 5] = sum;
    __syncthreads();
    sum = 0.f;
    #pragma unroll
    for (int i = 0; i < 8; i++) sum += sh[i];
    float inv = 1.f / sum;
    v.x *= inv; v.y *= inv; v.z *= inv; v.w *= inv;
    p[t] = v;
}

__global__ __launch_bounds__(128) void av_k(const float* __restrict__ sc,
                                            const float* __restrict__ V,
                                            float* __restrict__ o)
{
    int bh = blockIdx.x;
    int head = bh & (NHx - 1);
    int b = bh >> 3;
    int c = threadIdx.x;
    const float* vp = V + (size_t)b * Sx * Hx + (size_t)head * DHx + c;
    const float* ap = sc + (size_t)bh * Sx;
    float a0 = 0.f, a1 = 0.f, a2 = 0.f, a3 = 0.f;
    #pragma unroll 2
    for (int j = 0; j < Sx; j += 4) {
        a0 = fmaf(ap[j + 0], vp[(size_t)(j + 0) * Hx], a0);
        a1 = fmaf(ap[j + 1], vp[(size_t)(j + 1) * Hx], a1);
        a2 = fmaf(ap[j + 2], vp[(size_t)(j + 2) * Hx], a2);
        a3 = fmaf(ap[j + 3], vp[(size_t)(j + 3) * Hx], a3);
    }
    o[(size_t)b * Hx + head * DHx + c] = (a0 + a1) + (a2 + a3);
}

// ---------------- launch orchestration -------------------------------------
extern "C" void kernel_launch(void* const* d_in, const int* in_sizes, int n_in,
                              void* d_out, int out_size)
{
    const float* x    = (const float*)d_in[0];
    const float* Wf   = (const float*)d_in[1];
    const float* bf   = (const float*)d_in[2];
    const float* Wi   = (const float*)d_in[3];
    const float* bi   = (const float*)d_in[4];
    const float* Wh   = (const float*)d_in[5];
    const float* bh   = (const float*)d_in[6];
    const float* inw  = (const float*)d_in[7];
    const float* inb  = (const float*)d_in[8];
    const float* outw = (const float*)d_in[9];
    const float* outb = (const float*)d_in[10];
    const float* fcw  = (const float*)d_in[11];
    const float* fcb  = (const float*)d_in[12];
    float* out = (float*)d_out;

    float *bufA, *bufF, *bufI, *bufH, *chP, *chQ, *chS;
    float *scoresP, *qP, *oP, *lastP;
    __half *WHp, *WLp, *AHp, *ALp;
    cudaGetSymbolAddress((void**)&bufA, g_bufA);
    cudaGetSymbolAddress((void**)&bufF, g_bufF);
    cudaGetSymbolAddress((void**)&bufI, g_bufI);
    cudaGetSymbolAddress((void**)&bufH, g_bufH);
    cudaGetSymbolAddress((void**)&chP, g_chP);
    cudaGetSymbolAddress((void**)&chQ, g_chQ);
    cudaGetSymbolAddress((void**)&chS, g_chS);
    cudaGetSymbolAddress((void**)&scoresP, g_scores);
    cudaGetSymbolAddress((void**)&qP, g_q);
    cudaGetSymbolAddress((void**)&oP, g_o);
    cudaGetSymbolAddress((void**)&lastP, g_last);
    cudaGetSymbolAddress((void**)&WHp, g_WH);
    cudaGetSymbolAddress((void**)&WLp, g_WL);
    cudaGetSymbolAddress((void**)&AHp, g_AH);
    cudaGetSymbolAddress((void**)&ALp, g_AL);

    static int smemSet = 0;
    if (!smemSet) {
        cudaFuncSetAttribute(hgemm_k,
                             cudaFuncAttributeMaxDynamicSharedMemorySize, SMEMB);
        smemSet = 1;
    }

    // ---- conversions: weights (once per launch) + layer-0 activations
    conv_k<<<NWF / 4 / 256, 256>>>(Wf, WHp,            WLp,            NWF);
    conv_k<<<NWF / 4 / 256, 256>>>(Wi, WHp + NWF,      WLp + NWF,      NWF);
    conv_k<<<NWF / 4 / 256, 256>>>(Wh, WHp + 2 * NWF,  WLp + 2 * NWF,  NWF);
    conv_k<<<NWKV / 4 / 256, 256>>>(inw + (size_t)Hx * Hx,
                                    WHp + 3 * NWF, WLp + 3 * NWF, NWKV);
    conv_k<<<(Mx * Hx) / 4 / 256, 256>>>(x, AHp, ALp, Mx * Hx);

    dim3 gg(Hx / 128, Mx / 128);      // (8, 128)
    const int scanT = Bx * CC * Hx;   // 512K threads

    for (int l = 0; l < Lx; l++) {
        size_t wo = (size_t)l * Hx * Hx;
        hgemm_k<<<gg, 256, SMEMB>>>(AHp, ALp, WHp + wo,            WLp + wo,
                                    bf + (size_t)l * Hx, bufF);
        hgemm_k<<<gg, 256, SMEMB>>>(AHp, ALp, WHp + NWF + wo,      WLp + NWF + wo,
                                    bi + (size_t)l * Hx, bufI);
        hgemm_k<<<gg, 256, SMEMB>>>(AHp, ALp, WHp + 2 * NWF + wo,  WLp + 2 * NWF + wo,
                                    bh + (size_t)l * Hx, bufH);
        scan_p1<<<scanT / 256, 256>>>(bufF, bufI, bufH, bufF, bufI, chP, chQ);
        scan_p2<<<(Bx * Hx) / 256, 256>>>(chP, chQ, chS);
        scan_p3<<<scanT / 256, 256>>>(bufF, bufI, chS, bufA, AHp, ALp);
    }

    // Attention: K,V projections on tensor cores; only last query row matters.
    hgemm_k<<<gg, 256, SMEMB>>>(AHp, ALp, WHp + 3 * NWF, WLp + 3 * NWF,
                                inb + Hx, bufF);                      // K
    hgemm_k<<<gg, 256, SMEMB>>>(AHp, ALp, WHp + 3 * NWF + Hx * Hx,
                                WLp + 3 * NWF + Hx * Hx,
                                inb + 2 * Hx, bufI);                  // V

    vecmat_k<<<(Bx * Hx * 32 + 255) / 256, 256>>>(
        bufA + (size_t)(Sx - 1) * Hx, Sx * Hx, inw, inb, nullptr, 0, qP, Bx, Hx);

    scores_k<<<(Bx * NHx * Sx * 32) / 256, 256>>>(qP, bufF, scoresP);
    softmax_k<<<Bx * NHx, 256>>>(scoresP);
    av_k<<<Bx * NHx, 128>>>(scoresP, bufI, oP);

    vecmat_k<<<(Bx * Hx * 32 + 255) / 256, 256>>>(
        oP, Hx, outw, outb, bufA + (size_t)(Sx - 1) * Hx, Sx * Hx, lastP, Bx, Hx);
    vecmat_k<<<(Bx * Ox * 32 + 255) / 256, 256>>>(
        lastP, Hx, fcw, fcb, nullptr, 0, out, Bx, Ox);
}

// round 5
// speedup vs baseline: 3.3887x; 1.6255x over previous
#include <cuda_runtime.h>
#include <cuda_fp16.h>
#include <math.h>
#include <stdint.h>

// Problem constants
#define Bx  16
#define Sx  1024
#define Hx  1024
#define Ox  256
#define Lx  4
#define NHx 8
#define DHx 128
#define Mx  (Bx*Sx)   // 16384 rows
#define CT  32        // scan chunk length
#define CC  (Sx/CT)   // 32 chunks

typedef unsigned long long u64;

// ---------------- scratch (device globals: no allocation allowed) ----------
__device__ float g_bufA[(size_t)Mx * Hx];
__device__ float g_bufF[(size_t)Mx * Hx];
__device__ float g_bufI[(size_t)Mx * Hx];
__device__ float g_bufH[(size_t)Mx * Hx];
__device__ float g_chP[Bx * Hx * CC];
__device__ float g_chQ[Bx * Hx * CC];
__device__ float g_chS[Bx * Hx * CC];
__device__ float g_scores[Bx * NHx * Sx];
__device__ float g_q[Bx * Hx];
__device__ float g_o[Bx * Hx];
__device__ float g_last[Bx * Hx];

// fp16 hi/lo split buffers
#define NWF 4194304          // Wf total elems (4 layers)
#define NWKV 2097152         // K+V proj rows
#define NWTOT (3*NWF + NWKV) // 14680064
__device__ __half g_WH[NWTOT];
__device__ __half g_WL[NWTOT];
__device__ __half g_AH[(size_t)Mx * Hx];
__device__ __half g_AL[(size_t)Mx * Hx];

// ======================= helpers ===========================================
__device__ __forceinline__ uint32_t smem_u32(const void* p) {
    uint32_t a;
    asm("{ .reg .u64 t; cvta.to.shared.u64 t, %1; cvt.u32.u64 %0, t; }"
        : "=r"(a) : "l"(p));
    return a;
}
__device__ __forceinline__ void cpa16(uint32_t dst, const void* src) {
    asm volatile("cp.async.cg.shared.global [%0], [%1], 16;" :: "r"(dst), "l"(src));
}
__device__ __forceinline__ void ldm4(uint32_t& r0, uint32_t& r1,
                                     uint32_t& r2, uint32_t& r3, uint32_t a) {
    asm volatile("ldmatrix.sync.aligned.m8n8.x4.shared.b16 {%0,%1,%2,%3}, [%4];"
        : "=r"(r0), "=r"(r1), "=r"(r2), "=r"(r3) : "r"(a));
}
__device__ __forceinline__ void mma16816(float* d, const uint32_t* a, const uint32_t* b) {
    asm volatile("mma.sync.aligned.m16n8k16.row.col.f32.f16.f16.f32 "
        "{%0,%1,%2,%3}, {%4,%5,%6,%7}, {%8,%9}, {%0,%1,%2,%3};"
        : "+f"(d[0]), "+f"(d[1]), "+f"(d[2]), "+f"(d[3])
        : "r"(a[0]), "r"(a[1]), "r"(a[2]), "r"(a[3]), "r"(b[0]), "r"(b[1]));
}
__device__ __forceinline__ float fast_rcp(float x) {
    float r; asm("rcp.approx.f32 %0, %1;" : "=f"(r) : "f"(x)); return r;
}

// ======================= fused multi-output HGEMM ==========================
// For each region r (N-range of 1024): C_r = A * W_r^T + bias_r.
// A shared across regions. region = blockIdx.x >> 3.
// Products: hh + hl always; + lh iff (lhMask>>region)&1.
struct GemmArgs {
    const __half* WH[3];
    const __half* WL[3];
    const float*  bias[3];
    float*        C[3];
    unsigned      lhMask;
};

#define STG_SZ 32768
#define T_AH 0
#define T_AL 8192
#define T_BH 16384
#define T_BL 24576
#define SMEMB (3 * STG_SZ)

__global__ __launch_bounds__(256) void hgemm_fused_k(
    const __half* __restrict__ AH, const __half* __restrict__ AL, GemmArgs ga)
{
    extern __shared__ __align__(1024) char smem[];
    const uint32_t sb = smem_u32(smem);
    const int tid = threadIdx.x;
    const int wid = tid >> 5, lane = tid & 31;
    const int region = blockIdx.x >> 3;
    const int bx = blockIdx.x & 7;
    const int by = blockIdx.y;
    const bool do_lh = (ga.lhMask >> region) & 1u;

    const __half* WH = ga.WH[region];
    const __half* WL = ga.WL[region];
    const float*  bias = ga.bias[region];
    float*        C = ga.C[region];

    // ---- cp.async lane mapping: row lm, two 16B chunks
    const int lm  = tid >> 1;
    const int lc0 = (tid & 1) * 2;
    const size_t aoff = (size_t)(by * 128 + lm) * Hx;
    const size_t boff = (size_t)(bx * 128 + lm) * Hx;
    const int sws = (lm >> 1) & 3;
    const uint32_t d0 = lm * 64 + 16 * (lc0 ^ sws);
    const uint32_t d1 = lm * 64 + 16 * ((lc0 + 1) ^ sws);
    const int g0 = 8 * lc0, g1 = 8 * (lc0 + 1);

    #define LOAD_CHUNK(k0, s) do {                                          \
        uint32_t st_ = sb + (s) * STG_SZ;                                   \
        cpa16(st_ + T_AH + d0, AH + aoff + (k0) + g0);                      \
        cpa16(st_ + T_AH + d1, AH + aoff + (k0) + g1);                      \
        if (do_lh) {                                                        \
            cpa16(st_ + T_AL + d0, AL + aoff + (k0) + g0);                  \
            cpa16(st_ + T_AL + d1, AL + aoff + (k0) + g1);                  \
        }                                                                   \
        cpa16(st_ + T_BH + d0, WH + boff + (k0) + g0);                      \
        cpa16(st_ + T_BH + d1, WH + boff + (k0) + g1);                      \
        cpa16(st_ + T_BL + d0, WL + boff + (k0) + g0);                      \
        cpa16(st_ + T_BL + d1, WL + boff + (k0) + g1);                      \
        asm volatile("cp.async.commit_group;" ::: "memory");                \
    } while (0)

    // ---- mma lane geometry
    const int wm = (wid & 3) * 32;
    const int wn = (wid >> 2) * 64;
    const int ar0 = wm + (lane & 15);
    const int aK  = (lane >> 4) & 1;
    const int bK  = (lane >> 3) & 1;
    const int bnh = (lane >> 4) & 1;
    const int br0 = wn + (lane & 7);

    float acc[2][8][4];
    #pragma unroll
    for (int i = 0; i < 2; i++)
        #pragma unroll
        for (int j = 0; j < 8; j++)
            #pragma unroll
            for (int q = 0; q < 4; q++)
                acc[i][j][q] = 0.f;

    LOAD_CHUNK(0, 0);
    LOAD_CHUNK(32, 1);

    for (int c = 0; c < 32; c++) {
        const int s = c % 3;
        if (c < 31) asm volatile("cp.async.wait_group 1;" ::: "memory");
        else        asm volatile("cp.async.wait_group 0;" ::: "memory");
        __syncthreads();
        if (c + 2 < 32) LOAD_CHUNK((c + 2) * 32, (c + 2) % 3);

        const uint32_t st = sb + s * STG_SZ;
        #pragma unroll
        for (int kk = 0; kk < 2; kk++) {
            uint32_t ah[2][4], al[2][4], bh[8][2], bl[8][2];
            #pragma unroll
            for (int mt = 0; mt < 2; mt++) {
                const int row = ar0 + mt * 16;
                const uint32_t off = (uint32_t)(row * 64
                                   + 16 * ((kk * 2 + aK) ^ ((row >> 1) & 3)));
                ldm4(ah[mt][0], ah[mt][1], ah[mt][2], ah[mt][3], st + T_AH + off);
                if (do_lh)
                    ldm4(al[mt][0], al[mt][1], al[mt][2], al[mt][3], st + T_AL + off);
            }
            #pragma unroll
            for (int p = 0; p < 4; p++) {
                const int row = br0 + (p * 2 + bnh) * 8;
                const uint32_t off = (uint32_t)(row * 64
                                   + 16 * ((kk * 2 + bK) ^ ((row >> 1) & 3)));
                ldm4(bh[2*p][0], bh[2*p][1], bh[2*p+1][0], bh[2*p+1][1], st + T_BH + off);
                ldm4(bl[2*p][0], bl[2*p][1], bl[2*p+1][0], bl[2*p+1][1], st + T_BL + off);
            }
            // product 1: hi*hi
            #pragma unroll
            for (int mt = 0; mt < 2; mt++)
                #pragma unroll
                for (int nt = 0; nt < 8; nt++)
                    mma16816(acc[mt][nt], ah[mt], bh[nt]);
            // product 2: hi*lo
            #pragma unroll
            for (int mt = 0; mt < 2; mt++)
                #pragma unroll
                for (int nt = 0; nt < 8; nt++)
                    mma16816(acc[mt][nt], ah[mt], bl[nt]);
            // product 3: lo*hi (only for regions that need full accuracy)
            if (do_lh) {
                #pragma unroll
                for (int mt = 0; mt < 2; mt++)
                    #pragma unroll
                    for (int nt = 0; nt < 8; nt++)
                        mma16816(acc[mt][nt], al[mt], bh[nt]);
            }
        }
    }

    // ---- epilogue
    const int r0 = lane >> 2;
    const int cc = (lane & 3) * 2;
    #pragma unroll
    for (int mt = 0; mt < 2; mt++) {
        const int mrow = by * 128 + wm + mt * 16 + r0;
        #pragma unroll
        for (int nt = 0; nt < 8; nt++) {
            const int col = bx * 128 + wn + nt * 8 + cc;
            const float b0 = bias[col], b1 = bias[col + 1];
            float2 v0 = {acc[mt][nt][0] + b0, acc[mt][nt][1] + b1};
            float2 v1 = {acc[mt][nt][2] + b0, acc[mt][nt][3] + b1};
            *(float2*)&C[(size_t)mrow * Hx + col]       = v0;
            *(float2*)&C[(size_t)(mrow + 8) * Hx + col] = v1;
        }
    }
}

// ---------------- fp32 -> f16 hi/lo conversion -----------------------------
__global__ __launch_bounds__(256) void conv_k(
    const float* __restrict__ src, __half* __restrict__ hi,
    __half* __restrict__ lo, int n)
{
    int i = blockIdx.x * blockDim.x + threadIdx.x;
    if (i >= n / 4) return;
    float4 v = ((const float4*)src)[i];
    __half h0 = __float2half_rn(v.x), h1 = __float2half_rn(v.y);
    __half h2 = __float2half_rn(v.z), h3 = __float2half_rn(v.w);
    __half l0 = __float2half_rn(v.x - __half2float(h0));
    __half l1 = __float2half_rn(v.y - __half2float(h1));
    __half l2 = __float2half_rn(v.z - __half2float(h2));
    __half l3 = __float2half_rn(v.w - __half2float(h3));
    __half2* hp = (__half2*)hi;
    __half2* lp = (__half2*)lo;
    hp[i * 2]     = __halves2half2(h0, h1);
    hp[i * 2 + 1] = __halves2half2(h2, h3);
    lp[i * 2]     = __halves2half2(l0, l1);
    lp[i * 2 + 1] = __halves2half2(l2, l3);
}

// ---------------- chunked minLSTM scan -------------------------------------
__global__ __launch_bounds__(256) void scan_p1(
    const float* __restrict__ F, const float* __restrict__ I,
    const float* __restrict__ Ht, float* __restrict__ P, float* __restrict__ Q,
    float* __restrict__ chP, float* __restrict__ chQ)
{
    int t = blockIdx.x * blockDim.x + threadIdx.x;
    int h = t & (Hx - 1);
    int bc = t >> 10;
    int c = bc & (CC - 1);
    int b = bc >> 5;
    size_t base = ((size_t)b * Sx + (size_t)c * CT) * Hx + h;
    float accP = 1.f, accQ = 0.f;
    #pragma unroll 4
    for (int s = 0; s < CT; s++) {
        size_t idx = base + (size_t)s * Hx;
        float ea = __expf(F[idx]);
        float eb = __expf(I[idx]);
        float hv = Ht[idx];
        float na = ea * (1.f + eb);
        float nb = eb * (1.f + ea);
        float r = fast_rcp(na + nb);
        float p = na * r;
        float q = nb * r * hv;
        P[idx] = p; Q[idx] = q;
        accQ = fmaf(p, accQ, q);
        accP *= p;
    }
    chP[t] = accP;
    chQ[t] = accQ;
}

__global__ __launch_bounds__(256) void scan_p2(
    const float* __restrict__ chP, const float* __restrict__ chQ,
    float* __restrict__ chS)
{
    int u = blockIdx.x * blockDim.x + threadIdx.x;
    int h = u & (Hx - 1);
    int b = u >> 10;
    float hc = 0.f;
    #pragma unroll
    for (int c = 0; c < CC; c++) {
        size_t idx = ((size_t)b * CC + c) * Hx + h;
        chS[idx] = hc;
        hc = fmaf(chP[idx], hc, chQ[idx]);
    }
}

// pass3 also emits fp16 hi/lo of the activation for the next GEMM layer
__global__ __launch_bounds__(256) void scan_p3(
    const float* __restrict__ P, const float* __restrict__ Q,
    const float* __restrict__ chS, float* __restrict__ Out,
    __half* __restrict__ OH, __half* __restrict__ OL)
{
    int t = blockIdx.x * blockDim.x + threadIdx.x;
    int h = t & (Hx - 1);
    int bc = t >> 10;
    int c = bc & (CC - 1);
    int b = bc >> 5;
    size_t base = ((size_t)b * Sx + (size_t)c * CT) * Hx + h;
    float hp = chS[t];
    #pragma unroll 4
    for (int s = 0; s < CT; s++) {
        size_t idx = base + (size_t)s * Hx;
        hp = fmaf(P[idx], hp, Q[idx]);
        Out[idx] = hp;
        __half hh = __float2half_rn(hp);
        OH[idx] = hh;
        OL[idx] = __float2half_rn(hp - __half2float(hh));
    }
}

// ---------------- small vec-mat --------------------------------------------
__global__ void vecmat_k(const float* __restrict__ X, int xStride,
                         const float* __restrict__ W, const float* __restrict__ bias,
                         const float* __restrict__ res, int resStride,
                         float* __restrict__ out, int Bn, int N)
{
    int gw = (blockIdx.x * blockDim.x + threadIdx.x) >> 5;
    int lane = threadIdx.x & 31;
    if (gw >= Bn * N) return;
    int b = gw / N, n = gw % N;
    const float* xr = X + (size_t)b * xStride;
    const float* wr = W + (size_t)n * Hx;
    float s = 0.f;
    #pragma unroll
    for (int k = lane * 4; k < Hx; k += 128) {
        float4 xv = *(const float4*)(xr + k);
        float4 wv = *(const float4*)(wr + k);
        s += xv.x * wv.x + xv.y * wv.y + xv.z * wv.z + xv.w * wv.w;
    }
    #pragma unroll
    for (int o = 16; o; o >>= 1) s += __shfl_xor_sync(0xffffffffu, s, o);
    if (lane == 0) {
        float v = s + bias[n];
        if (res) v += res[(size_t)b * resStride + n];
        out[(size_t)b * N + n] = v;
    }
}

// ---------------- attention (last query row only) --------------------------
__global__ void scores_k(const float* __restrict__ q, const float* __restrict__ Kb,
                         float* __restrict__ sc)
{
    int gw = (blockIdx.x * blockDim.x + threadIdx.x) >> 5;
    int lane = threadIdx.x & 31;
    if (gw >= Bx * NHx * Sx) return;
    int j = gw & (Sx - 1);
    int bh = gw >> 10;
    int head = bh & (NHx - 1);
    int b = bh >> 3;
    const float4* qr = (const float4*)(q + (size_t)b * Hx + head * DHx);
    const float4* kr = (const float4*)(Kb + ((size_t)b * Sx + j) * Hx + head * DHx);
    float4 qv = qr[lane], kv = kr[lane];
    float s = qv.x * kv.x + qv.y * kv.y + qv.z * kv.z + qv.w * kv.w;
    #pragma unroll
    for (int o = 16; o; o >>= 1) s += __shfl_xor_sync(0xffffffffu, s, o);
    if (lane == 0) sc[(size_t)bh * Sx + j] = s * 0.0883883476483184f;
}

__global__ __launch_bounds__(256) void softmax_k(float* __restrict__ sc)
{
    int row = blockIdx.x;
    float4* p = (float4*)(sc + (size_t)row * Sx);
    int t = threadIdx.x;
    float4 v = p[t];
    __shared__ float sh[8];

    float m = fmaxf(fmaxf(v.x, v.y), fmaxf(v.z, v.w));
    #pragma unroll
    for (int o = 16; o; o >>= 1) m = fmaxf(m, __shfl_xor_sync(0xffffffffu, m, o));
    if ((t & 31) == 0) sh[t >> 5] = m;
    __syncthreads();
    m = sh[0];
    #pragma unroll
    for (int i = 1; i < 8; i++) m = fmaxf(m, sh[i]);

    v.x = __expf(v.x - m); v.y = __expf(v.y - m);
    v.z = __expf(v.z - m); v.w = __expf(v.w - m);
    float sum = v.x + v.y + v.z + v.w;
    #pragma unroll
    for (int o = 16; o; o >>= 1) sum += __shfl_xor_sync(0xffffffffu, sum, o);
    __syncthreads();
    if ((t & 31) == 0) sh[t >> 5] = sum;
    __syncthreads();
    sum = 0.f;
    #pragma unroll
    for (int i = 0; i < 8; i++) sum += sh[i];
    float inv = 1.f / sum;
    v.x *= inv; v.y *= inv; v.z *= inv; v.w *= inv;
    p[t] = v;
}

__global__ __launch_bounds__(128) void av_k(const float* __restrict__ sc,
                                            const float* __restrict__ V,
                                            float* __restrict__ o)
{
    int bh = blockIdx.x;
    int head = bh & (NHx - 1);
    int b = bh >> 3;
    int c = threadIdx.x;
    const float* vp = V + (size_t)b * Sx * Hx + (size_t)head * DHx + c;
    const float* ap = sc + (size_t)bh * Sx;
    float a0 = 0.f, a1 = 0.f, a2 = 0.f, a3 = 0.f;
    #pragma unroll 2
    for (int j = 0; j < Sx; j += 4) {
        a0 = fmaf(ap[j + 0], vp[(size_t)(j + 0) * Hx], a0);
        a1 = fmaf(ap[j + 1], vp[(size_t)(j + 1) * Hx], a1);
        a2 = fmaf(ap[j + 2], vp[(size_t)(j + 2) * Hx], a2);
        a3 = fmaf(ap[j + 3], vp[(size_t)(j + 3) * Hx], a3);
    }
    o[(size_t)b * Hx + head * DHx + c] = (a0 + a1) + (a2 + a3);
}

// ---------------- launch orchestration -------------------------------------
extern "C" void kernel_launch(void* const* d_in, const int* in_sizes, int n_in,
                              void* d_out, int out_size)
{
    const float* x    = (const float*)d_in[0];
    const float* Wf   = (const float*)d_in[1];
    const float* bf   = (const float*)d_in[2];
    const float* Wi   = (const float*)d_in[3];
    const float* bi   = (const float*)d_in[4];
    const float* Wh   = (const float*)d_in[5];
    const float* bh   = (const float*)d_in[6];
    const float* inw  = (const float*)d_in[7];
    const float* inb  = (const float*)d_in[8];
    const float* outw = (const float*)d_in[9];
    const float* outb = (const float*)d_in[10];
    const float* fcw  = (const float*)d_in[11];
    const float* fcb  = (const float*)d_in[12];
    float* out = (float*)d_out;

    float *bufA, *bufF, *bufI, *bufH, *chP, *chQ, *chS;
    float *scoresP, *qP, *oP, *lastP;
    __half *WHp, *WLp, *AHp, *ALp;
    cudaGetSymbolAddress((void**)&bufA, g_bufA);
    cudaGetSymbolAddress((void**)&bufF, g_bufF);
    cudaGetSymbolAddress((void**)&bufI, g_bufI);
    cudaGetSymbolAddress((void**)&bufH, g_bufH);
    cudaGetSymbolAddress((void**)&chP, g_chP);
    cudaGetSymbolAddress((void**)&chQ, g_chQ);
    cudaGetSymbolAddress((void**)&chS, g_chS);
    cudaGetSymbolAddress((void**)&scoresP, g_scores);
    cudaGetSymbolAddress((void**)&qP, g_q);
    cudaGetSymbolAddress((void**)&oP, g_o);
    cudaGetSymbolAddress((void**)&lastP, g_last);
    cudaGetSymbolAddress((void**)&WHp, g_WH);
    cudaGetSymbolAddress((void**)&WLp, g_WL);
    cudaGetSymbolAddress((void**)&AHp, g_AH);
    cudaGetSymbolAddress((void**)&ALp, g_AL);

    static int smemSet = 0;
    if (!smemSet) {
        cudaFuncSetAttribute(hgemm_fused_k,
                             cudaFuncAttributeMaxDynamicSharedMemorySize, SMEMB);
        smemSet = 1;
    }

    // ---- conversions: weights (once per launch) + layer-0 activations
    conv_k<<<NWF / 4 / 256, 256>>>(Wf, WHp,            WLp,            NWF);
    conv_k<<<NWF / 4 / 256, 256>>>(Wi, WHp + NWF,      WLp + NWF,      NWF);
    conv_k<<<NWF / 4 / 256, 256>>>(Wh, WHp + 2 * NWF,  WLp + 2 * NWF,  NWF);
    conv_k<<<NWKV / 4 / 256, 256>>>(inw + (size_t)Hx * Hx,
                                    WHp + 3 * NWF, WLp + 3 * NWF, NWKV);
    conv_k<<<(Mx * Hx) / 4 / 256, 256>>>(x, AHp, ALp, Mx * Hx);

    dim3 gl(24, 128);                 // fused f,i,h GEMM
    dim3 gkv(16, 128);                // fused K,V GEMM
    const int scanT = Bx * CC * Hx;   // 512K threads

    for (int l = 0; l < Lx; l++) {
        size_t wo = (size_t)l * Hx * Hx;
        GemmArgs ga;
        ga.WH[0] = WHp + wo;           ga.WL[0] = WLp + wo;
        ga.WH[1] = WHp + NWF + wo;     ga.WL[1] = WLp + NWF + wo;
        ga.WH[2] = WHp + 2 * NWF + wo; ga.WL[2] = WLp + 2 * NWF + wo;
        ga.bias[0] = bf + (size_t)l * Hx;
        ga.bias[1] = bi + (size_t)l * Hx;
        ga.bias[2] = bh + (size_t)l * Hx;
        ga.C[0] = bufF; ga.C[1] = bufI; ga.C[2] = bufH;
        ga.lhMask = 0x4;   // full 3-product only for h_tilde
        hgemm_fused_k<<<gl, 256, SMEMB>>>(AHp, ALp, ga);
        scan_p1<<<scanT / 256, 256>>>(bufF, bufI, bufH, bufF, bufI, chP, chQ);
        scan_p2<<<(Bx * Hx) / 256, 256>>>(chP, chQ, chS);
        scan_p3<<<scanT / 256, 256>>>(bufF, bufI, chS, bufA, AHp, ALp);
    }

    // Attention: K,V projections (full accuracy); only last query row matters.
    {
        GemmArgs ga;
        ga.WH[0] = WHp + 3 * NWF;               ga.WL[0] = WLp + 3 * NWF;
        ga.WH[1] = WHp + 3 * NWF + Hx * Hx;     ga.WL[1] = WLp + 3 * NWF + Hx * Hx;
        ga.WH[2] = nullptr;                     ga.WL[2] = nullptr;
        ga.bias[0] = inb + Hx;  ga.bias[1] = inb + 2 * Hx;  ga.bias[2] = nullptr;
        ga.C[0] = bufF; ga.C[1] = bufI; ga.C[2] = nullptr;
        ga.lhMask = 0x3;
        hgemm_fused_k<<<gkv, 256, SMEMB>>>(AHp, ALp, ga);
    }

    vecmat_k<<<(Bx * Hx * 32 + 255) / 256, 256>>>(
        bufA + (size_t)(Sx - 1) * Hx, Sx * Hx, inw, inb, nullptr, 0, qP, Bx, Hx);

    scores_k<<<(Bx * NHx * Sx * 32) / 256, 256>>>(qP, bufF, scoresP);
    softmax_k<<<Bx * NHx, 256>>>(scoresP);
    av_k<<<Bx * NHx, 128>>>(scoresP, bufI, oP);

    vecmat_k<<<(Bx * Hx * 32 + 255) / 256, 256>>>(
        oP, Hx, outw, outb, bufA + (size_t)(Sx - 1) * Hx, Sx * Hx, lastP, Bx, Hx);
    vecmat_k<<<(Bx * Ox * 32 + 255) / 256, 256>>>(
        lastP, Hx, fcw, fcb, nullptr, 0, out, Bx, Ox);
}

// round 6
// speedup vs baseline: 3.6818x; 1.0865x over previous
#include <cuda_runtime.h>
#include <cuda_fp16.h>
#include <math.h>
#include <stdint.h>

// Problem constants
#define Bx  16
#define Sx  1024
#define Hx  1024
#define Ox  256
#define Lx  4
#define NHx 8
#define DHx 128
#define Mx  (Bx*Sx)   // 16384 rows
#define CT  32        // scan chunk length
#define CC  (Sx/CT)   // 32 chunks

typedef unsigned long long u64;

// ---------------- scratch (device globals: no allocation allowed) ----------
__device__ float g_bufA[(size_t)Mx * Hx];
__device__ float g_bufF[(size_t)Mx * Hx];
__device__ float g_bufI[(size_t)Mx * Hx];
__device__ float g_bufH[(size_t)Mx * Hx];
__device__ float g_chP[Bx * Hx * CC];
__device__ float g_chQ[Bx * Hx * CC];
__device__ float g_chS[Bx * Hx * CC];
__device__ float g_scores[Bx * NHx * Sx];
__device__ float g_q[Bx * Hx];
__device__ float g_o[Bx * Hx];
__device__ float g_last[Bx * Hx];

// fp16 hi/lo split buffers
#define NWF 4194304          // Wf total elems (4 layers)
#define NWKV 2097152         // K+V proj rows
#define NWTOT (3*NWF + NWKV) // 14680064
__device__ __half g_WH[NWTOT];
__device__ __half g_WL[NWTOT];
__device__ __half g_AH[(size_t)Mx * Hx];
__device__ __half g_AL[(size_t)Mx * Hx];

// ======================= helpers ===========================================
__device__ __forceinline__ uint32_t smem_u32(const void* p) {
    uint32_t a;
    asm("{ .reg .u64 t; cvta.to.shared.u64 t, %1; cvt.u32.u64 %0, t; }"
        : "=r"(a) : "l"(p));
    return a;
}
__device__ __forceinline__ void cpa16(uint32_t dst, const void* src) {
    asm volatile("cp.async.cg.shared.global [%0], [%1], 16;" :: "r"(dst), "l"(src));
}
__device__ __forceinline__ void ldm4(uint32_t& r0, uint32_t& r1,
                                     uint32_t& r2, uint32_t& r3, uint32_t a) {
    asm volatile("ldmatrix.sync.aligned.m8n8.x4.shared.b16 {%0,%1,%2,%3}, [%4];"
        : "=r"(r0), "=r"(r1), "=r"(r2), "=r"(r3) : "r"(a));
}
__device__ __forceinline__ void mma16816(float* d, const uint32_t* a, const uint32_t* b) {
    asm volatile("mma.sync.aligned.m16n8k16.row.col.f32.f16.f16.f32 "
        "{%0,%1,%2,%3}, {%4,%5,%6,%7}, {%8,%9}, {%0,%1,%2,%3};"
        : "+f"(d[0]), "+f"(d[1]), "+f"(d[2]), "+f"(d[3])
        : "r"(a[0]), "r"(a[1]), "r"(a[2]), "r"(a[3]), "r"(b[0]), "r"(b[1]));
}
__device__ __forceinline__ float fast_rcp(float x) {
    float r; asm("rcp.approx.f32 %0, %1;" : "=f"(r) : "f"(x)); return r;
}

// ======================= fused multi-output HGEMM ==========================
// For each region r (N-range of 1024): C_r = A * W_r^T + bias_r.
// A shared across regions. region = blockIdx.x >> 3.
// Products: hh + hl always; + lh iff (lhMask>>region)&1.
struct GemmArgs {
    const __half* WH[3];
    const __half* WL[3];
    const float*  bias[3];
    float*        C[3];
    unsigned      lhMask;
};

#define STG_SZ 32768
#define T_AH 0
#define T_AL 8192
#define T_BH 16384
#define T_BL 24576
#define SMEMB (3 * STG_SZ)

__global__ __launch_bounds__(256) void hgemm_fused_k(
    const __half* __restrict__ AH, const __half* __restrict__ AL, GemmArgs ga)
{
    extern __shared__ __align__(1024) char smem[];
    const uint32_t sb = smem_u32(smem);
    const int tid = threadIdx.x;
    const int wid = tid >> 5, lane = tid & 31;
    const int region = blockIdx.x >> 3;
    const int bx = blockIdx.x & 7;
    const int by = blockIdx.y;
    const bool do_lh = (ga.lhMask >> region) & 1u;

    const __half* WH = ga.WH[region];
    const __half* WL = ga.WL[region];
    const float*  bias = ga.bias[region];
    float*        C = ga.C[region];

    // ---- cp.async lane mapping: row lm, two 16B chunks
    const int lm  = tid >> 1;
    const int lc0 = (tid & 1) * 2;
    const size_t aoff = (size_t)(by * 128 + lm) * Hx;
    const size_t boff = (size_t)(bx * 128 + lm) * Hx;
    const int sws = (lm >> 1) & 3;
    const uint32_t d0 = lm * 64 + 16 * (lc0 ^ sws);
    const uint32_t d1 = lm * 64 + 16 * ((lc0 + 1) ^ sws);
    const int g0 = 8 * lc0, g1 = 8 * (lc0 + 1);

    #define LOAD_CHUNK(k0, s) do {                                          \
        uint32_t st_ = sb + (s) * STG_SZ;                                   \
        cpa16(st_ + T_AH + d0, AH + aoff + (k0) + g0);                      \
        cpa16(st_ + T_AH + d1, AH + aoff + (k0) + g1);                      \
        if (do_lh) {                                                        \
            cpa16(st_ + T_AL + d0, AL + aoff + (k0) + g0);                  \
            cpa16(st_ + T_AL + d1, AL + aoff + (k0) + g1);                  \
        }                                                                   \
        cpa16(st_ + T_BH + d0, WH + boff + (k0) + g0);                      \
        cpa16(st_ + T_BH + d1, WH + boff + (k0) + g1);                      \
        cpa16(st_ + T_BL + d0, WL + boff + (k0) + g0);                      \
        cpa16(st_ + T_BL + d1, WL + boff + (k0) + g1);                      \
        asm volatile("cp.async.commit_group;" ::: "memory");                \
    } while (0)

    // ---- mma lane geometry
    const int wm = (wid & 3) * 32;
    const int wn = (wid >> 2) * 64;
    const int ar0 = wm + (lane & 15);
    const int aK  = (lane >> 4) & 1;
    const int bK  = (lane >> 3) & 1;
    const int bnh = (lane >> 4) & 1;
    const int br0 = wn + (lane & 7);

    float acc[2][8][4];
    #pragma unroll
    for (int i = 0; i < 2; i++)
        #pragma unroll
        for (int j = 0; j < 8; j++)
            #pragma unroll
            for (int q = 0; q < 4; q++)
                acc[i][j][q] = 0.f;

    LOAD_CHUNK(0, 0);
    LOAD_CHUNK(32, 1);

    for (int c = 0; c < 32; c++) {
        const int s = c % 3;
        if (c < 31) asm volatile("cp.async.wait_group 1;" ::: "memory");
        else        asm volatile("cp.async.wait_group 0;" ::: "memory");
        __syncthreads();
        if (c + 2 < 32) LOAD_CHUNK((c + 2) * 32, (c + 2) % 3);

        const uint32_t st = sb + s * STG_SZ;
        #pragma unroll
        for (int kk = 0; kk < 2; kk++) {
            uint32_t ah[2][4], al[2][4], bh[8][2], bl[8][2];
            #pragma unroll
            for (int mt = 0; mt < 2; mt++) {
                const int row = ar0 + mt * 16;
                const uint32_t off = (uint32_t)(row * 64
                                   + 16 * ((kk * 2 + aK) ^ ((row >> 1) & 3)));
                ldm4(ah[mt][0], ah[mt][1], ah[mt][2], ah[mt][3], st + T_AH + off);
                if (do_lh)
                    ldm4(al[mt][0], al[mt][1], al[mt][2], al[mt][3], st + T_AL + off);
            }
            #pragma unroll
            for (int p = 0; p < 4; p++) {
                const int row = br0 + (p * 2 + bnh) * 8;
                const uint32_t off = (uint32_t)(row * 64
                                   + 16 * ((kk * 2 + bK) ^ ((row >> 1) & 3)));
                ldm4(bh[2*p][0], bh[2*p][1], bh[2*p+1][0], bh[2*p+1][1], st + T_BH + off);
                ldm4(bl[2*p][0], bl[2*p][1], bl[2*p+1][0], bl[2*p+1][1], st + T_BL + off);
            }
            // product 1: hi*hi
            #pragma unroll
            for (int mt = 0; mt < 2; mt++)
                #pragma unroll
                for (int nt = 0; nt < 8; nt++)
                    mma16816(acc[mt][nt], ah[mt], bh[nt]);
            // product 2: hi*lo
            #pragma unroll
            for (int mt = 0; mt < 2; mt++)
                #pragma unroll
                for (int nt = 0; nt < 8; nt++)
                    mma16816(acc[mt][nt], ah[mt], bl[nt]);
            // product 3: lo*hi (only for regions that need full accuracy)
            if (do_lh) {
                #pragma unroll
                for (int mt = 0; mt < 2; mt++)
                    #pragma unroll
                    for (int nt = 0; nt < 8; nt++)
                        mma16816(acc[mt][nt], al[mt], bh[nt]);
            }
        }
    }

    // ---- epilogue
    const int r0 = lane >> 2;
    const int cc = (lane & 3) * 2;
    #pragma unroll
    for (int mt = 0; mt < 2; mt++) {
        const int mrow = by * 128 + wm + mt * 16 + r0;
        #pragma unroll
        for (int nt = 0; nt < 8; nt++) {
            const int col = bx * 128 + wn + nt * 8 + cc;
            const float b0 = bias[col], b1 = bias[col + 1];
            float2 v0 = {acc[mt][nt][0] + b0, acc[mt][nt][1] + b1};
            float2 v1 = {acc[mt][nt][2] + b0, acc[mt][nt][3] + b1};
            *(float2*)&C[(size_t)mrow * Hx + col]       = v0;
            *(float2*)&C[(size_t)(mrow + 8) * Hx + col] = v1;
        }
    }
}

// ---------------- fp32 -> f16 hi/lo conversion -----------------------------
__global__ __launch_bounds__(256) void conv_k(
    const float* __restrict__ src, __half* __restrict__ hi,
    __half* __restrict__ lo, int n)
{
    int i = blockIdx.x * blockDim.x + threadIdx.x;
    if (i >= n / 4) return;
    float4 v = ((const float4*)src)[i];
    __half h0 = __float2half_rn(v.x), h1 = __float2half_rn(v.y);
    __half h2 = __float2half_rn(v.z), h3 = __float2half_rn(v.w);
    __half l0 = __float2half_rn(v.x - __half2float(h0));
    __half l1 = __float2half_rn(v.y - __half2float(h1));
    __half l2 = __float2half_rn(v.z - __half2float(h2));
    __half l3 = __float2half_rn(v.w - __half2float(h3));
    __half2* hp = (__half2*)hi;
    __half2* lp = (__half2*)lo;
    hp[i * 2]     = __halves2half2(h0, h1);
    hp[i * 2 + 1] = __halves2half2(h2, h3);
    lp[i * 2]     = __halves2half2(l0, l1);
    lp[i * 2 + 1] = __halves2half2(l2, l3);
}

// ---------------- chunked minLSTM scan -------------------------------------
__global__ __launch_bounds__(256) void scan_p1(
    const float* __restrict__ F, const float* __restrict__ I,
    const float* __restrict__ Ht, float* __restrict__ P, float* __restrict__ Q,
    float* __restrict__ chP, float* __restrict__ chQ)
{
    int t = blockIdx.x * blockDim.x + threadIdx.x;
    int h = t & (Hx - 1);
    int bc = t >> 10;
    int c = bc & (CC - 1);
    int b = bc >> 5;
    size_t base = ((size_t)b * Sx + (size_t)c * CT) * Hx + h;
    float accP = 1.f, accQ = 0.f;
    #pragma unroll 4
    for (int s = 0; s < CT; s++) {
        size_t idx = base + (size_t)s * Hx;
        float ea = __expf(F[idx]);
        float eb = __expf(I[idx]);
        float hv = Ht[idx];
        float na = ea * (1.f + eb);
        float nb = eb * (1.f + ea);
        float r = fast_rcp(na + nb);
        float p = na * r;
        float q = nb * r * hv;
        P[idx] = p; Q[idx] = q;
        accQ = fmaf(p, accQ, q);
        accP *= p;
    }
    chP[t] = accP;
    chQ[t] = accQ;
}

__global__ __launch_bounds__(256) void scan_p2(
    const float* __restrict__ chP, const float* __restrict__ chQ,
    float* __restrict__ chS)
{
    int u = blockIdx.x * blockDim.x + threadIdx.x;
    int h = u & (Hx - 1);
    int b = u >> 10;
    float hc = 0.f;
    #pragma unroll
    for (int c = 0; c < CC; c++) {
        size_t idx = ((size_t)b * CC + c) * Hx + h;
        chS[idx] = hc;
        hc = fmaf(chP[idx], hc, chQ[idx]);
    }
}

// pass3: apply scan; emit fp16 hi (always) and lo (only when needed downstream)
__global__ __launch_bounds__(256) void scan_p3(
    const float* __restrict__ P, const float* __restrict__ Q,
    const float* __restrict__ chS, float* __restrict__ Out,
    __half* __restrict__ OH, __half* __restrict__ OL, int writeLo)
{
    int t = blockIdx.x * blockDim.x + threadIdx.x;
    int h = t & (Hx - 1);
    int bc = t >> 10;
    int c = bc & (CC - 1);
    int b = bc >> 5;
    size_t base = ((size_t)b * Sx + (size_t)c * CT) * Hx + h;
    float hp = chS[t];
    #pragma unroll 4
    for (int s = 0; s < CT; s++) {
        size_t idx = base + (size_t)s * Hx;
        hp = fmaf(P[idx], hp, Q[idx]);
        Out[idx] = hp;
        __half hh = __float2half_rn(hp);
        OH[idx] = hh;
        if (writeLo) OL[idx] = __float2half_rn(hp - __half2float(hh));
    }
}

// ---------------- small vec-mat --------------------------------------------
__global__ void vecmat_k(const float* __restrict__ X, int xStride,
                         const float* __restrict__ W, const float* __restrict__ bias,
                         const float* __restrict__ res, int resStride,
                         float* __restrict__ out, int Bn, int N)
{
    int gw = (blockIdx.x * blockDim.x + threadIdx.x) >> 5;
    int lane = threadIdx.x & 31;
    if (gw >= Bn * N) return;
    int b = gw / N, n = gw % N;
    const float* xr = X + (size_t)b * xStride;
    const float* wr = W + (size_t)n * Hx;
    float s = 0.f;
    #pragma unroll
    for (int k = lane * 4; k < Hx; k += 128) {
        float4 xv = *(const float4*)(xr + k);
        float4 wv = *(const float4*)(wr + k);
        s += xv.x * wv.x + xv.y * wv.y + xv.z * wv.z + xv.w * wv.w;
    }
    #pragma unroll
    for (int o = 16; o; o >>= 1) s += __shfl_xor_sync(0xffffffffu, s, o);
    if (lane == 0) {
        float v = s + bias[n];
        if (res) v += res[(size_t)b * resStride + n];
        out[(size_t)b * N + n] = v;
    }
}

// ---------------- attention (last query row only) --------------------------
__global__ void scores_k(const float* __restrict__ q, const float* __restrict__ Kb,
                         float* __restrict__ sc)
{
    int gw = (blockIdx.x * blockDim.x + threadIdx.x) >> 5;
    int lane = threadIdx.x & 31;
    if (gw >= Bx * NHx * Sx) return;
    int j = gw & (Sx - 1);
    int bh = gw >> 10;
    int head = bh & (NHx - 1);
    int b = bh >> 3;
    const float4* qr = (const float4*)(q + (size_t)b * Hx + head * DHx);
    const float4* kr = (const float4*)(Kb + ((size_t)b * Sx + j) * Hx + head * DHx);
    float4 qv = qr[lane], kv = kr[lane];
    float s = qv.x * kv.x + qv.y * kv.y + qv.z * kv.z + qv.w * kv.w;
    #pragma unroll
    for (int o = 16; o; o >>= 1) s += __shfl_xor_sync(0xffffffffu, s, o);
    if (lane == 0) sc[(size_t)bh * Sx + j] = s * 0.0883883476483184f;
}

__global__ __launch_bounds__(256) void softmax_k(float* __restrict__ sc)
{
    int row = blockIdx.x;
    float4* p = (float4*)(sc + (size_t)row * Sx);
    int t = threadIdx.x;
    float4 v = p[t];
    __shared__ float sh[8];

    float m = fmaxf(fmaxf(v.x, v.y), fmaxf(v.z, v.w));
    #pragma unroll
    for (int o = 16; o; o >>= 1) m = fmaxf(m, __shfl_xor_sync(0xffffffffu, m, o));
    if ((t & 31) == 0) sh[t >> 5] = m;
    __syncthreads();
    m = sh[0];
    #pragma unroll
    for (int i = 1; i < 8; i++) m = fmaxf(m, sh[i]);

    v.x = __expf(v.x - m); v.y = __expf(v.y - m);
    v.z = __expf(v.z - m); v.w = __expf(v.w - m);
    float sum = v.x + v.y + v.z + v.w;
    #pragma unroll
    for (int o = 16; o; o >>= 1) sum += __shfl_xor_sync(0xffffffffu, sum, o);
    __syncthreads();
    if ((t & 31) == 0) sh[t >> 5] = sum;
    __syncthreads();
    sum = 0.f;
    #pragma unroll
    for (int i = 0; i < 8; i++) sum += sh[i];
    float inv = 1.f / sum;
    v.x *= inv; v.y *= inv; v.z *= inv; v.w *= inv;
    p[t] = v;
}

// attn @ V for last query row; 512 threads: c=tid&127, j-group=tid>>7
__global__ __launch_bounds__(512) void av_k(const float* __restrict__ sc,
                                            const float* __restrict__ V,
                                            float* __restrict__ o)
{
    int bh = blockIdx.x;
    int head = bh & (NHx - 1);
    int b = bh >> 3;
    int c = threadIdx.x & 127;
    int jg = threadIdx.x >> 7;   // 0..3
    const float* vp = V + (size_t)b * Sx * Hx + (size_t)head * DHx + c;
    const float* ap = sc + (size_t)bh * Sx;
    float a0 = 0.f, a1 = 0.f;
    const int j0 = jg * 256;
    #pragma unroll 4
    for (int j = j0; j < j0 + 256; j += 2) {
        a0 = fmaf(ap[j + 0], vp[(size_t)(j + 0) * Hx], a0);
        a1 = fmaf(ap[j + 1], vp[(size_t)(j + 1) * Hx], a1);
    }
    __shared__ float sh[512];
    sh[threadIdx.x] = a0 + a1;
    __syncthreads();
    if (jg == 0)
        o[(size_t)b * Hx + head * DHx + c] =
            (sh[c] + sh[c + 128]) + (sh[c + 256] + sh[c + 384]);
}

// ---------------- launch orchestration -------------------------------------
extern "C" void kernel_launch(void* const* d_in, const int* in_sizes, int n_in,
                              void* d_out, int out_size)
{
    const float* x    = (const float*)d_in[0];
    const float* Wf   = (const float*)d_in[1];
    const float* bf   = (const float*)d_in[2];
    const float* Wi   = (const float*)d_in[3];
    const float* bi   = (const float*)d_in[4];
    const float* Wh   = (const float*)d_in[5];
    const float* bh   = (const float*)d_in[6];
    const float* inw  = (const float*)d_in[7];
    const float* inb  = (const float*)d_in[8];
    const float* outw = (const float*)d_in[9];
    const float* outb = (const float*)d_in[10];
    const float* fcw  = (const float*)d_in[11];
    const float* fcb  = (const float*)d_in[12];
    float* out = (float*)d_out;

    float *bufA, *bufF, *bufI, *bufH, *chP, *chQ, *chS;
    float *scoresP, *qP, *oP, *lastP;
    __half *WHp, *WLp, *AHp, *ALp;
    cudaGetSymbolAddress((void**)&bufA, g_bufA);
    cudaGetSymbolAddress((void**)&bufF, g_bufF);
    cudaGetSymbolAddress((void**)&bufI, g_bufI);
    cudaGetSymbolAddress((void**)&bufH, g_bufH);
    cudaGetSymbolAddress((void**)&chP, g_chP);
    cudaGetSymbolAddress((void**)&chQ, g_chQ);
    cudaGetSymbolAddress((void**)&chS, g_chS);
    cudaGetSymbolAddress((void**)&scoresP, g_scores);
    cudaGetSymbolAddress((void**)&qP, g_q);
    cudaGetSymbolAddress((void**)&oP, g_o);
    cudaGetSymbolAddress((void**)&lastP, g_last);
    cudaGetSymbolAddress((void**)&WHp, g_WH);
    cudaGetSymbolAddress((void**)&WLp, g_WL);
    cudaGetSymbolAddress((void**)&AHp, g_AH);
    cudaGetSymbolAddress((void**)&ALp, g_AL);

    static int smemSet = 0;
    if (!smemSet) {
        cudaFuncSetAttribute(hgemm_fused_k,
                             cudaFuncAttributeMaxDynamicSharedMemorySize, SMEMB);
        smemSet = 1;
    }

    // ---- conversions: weights (once per launch) + layer-0 activations
    conv_k<<<NWF / 4 / 256, 256>>>(Wf, WHp,            WLp,            NWF);
    conv_k<<<NWF / 4 / 256, 256>>>(Wi, WHp + NWF,      WLp + NWF,      NWF);
    conv_k<<<NWF / 4 / 256, 256>>>(Wh, WHp + 2 * NWF,  WLp + 2 * NWF,  NWF);
    conv_k<<<NWKV / 4 / 256, 256>>>(inw + (size_t)Hx * Hx,
                                    WHp + 3 * NWF, WLp + 3 * NWF, NWKV);
    conv_k<<<(Mx * Hx) / 4 / 256, 256>>>(x, AHp, ALp, Mx * Hx);

    dim3 gl(24, 128);                 // fused f,i,h GEMM
    dim3 gkv(16, 128);                // fused K,V GEMM
    const int scanT = Bx * CC * Hx;   // 512K threads

    for (int l = 0; l < Lx; l++) {
        size_t wo = (size_t)l * Hx * Hx;
        GemmArgs ga;
        ga.WH[0] = WHp + wo;           ga.WL[0] = WLp + wo;
        ga.WH[1] = WHp + NWF + wo;     ga.WL[1] = WLp + NWF + wo;
        ga.WH[2] = WHp + 2 * NWF + wo; ga.WL[2] = WLp + 2 * NWF + wo;
        ga.bias[0] = bf + (size_t)l * Hx;
        ga.bias[1] = bi + (size_t)l * Hx;
        ga.bias[2] = bh + (size_t)l * Hx;
        ga.C[0] = bufF; ga.C[1] = bufI; ga.C[2] = bufH;
        ga.lhMask = 0x0;   // 2-product everywhere in LSTM (budgeted)
        hgemm_fused_k<<<gl, 256, SMEMB>>>(AHp, ALp, ga);
        scan_p1<<<scanT / 256, 256>>>(bufF, bufI, bufH, bufF, bufI, chP, chQ);
        scan_p2<<<(Bx * Hx) / 256, 256>>>(chP, chQ, chS);
        scan_p3<<<scanT / 256, 256>>>(bufF, bufI, chS, bufA, AHp, ALp,
                                      (l == Lx - 1) ? 1 : 0);
    }

    // Attention: K,V projections (full 3-product accuracy).
    {
        GemmArgs ga;
        ga.WH[0] = WHp + 3 * NWF;               ga.WL[0] = WLp + 3 * NWF;
        ga.WH[1] = WHp + 3 * NWF + Hx * Hx;     ga.WL[1] = WLp + 3 * NWF + Hx * Hx;
        ga.WH[2] = nullptr;                     ga.WL[2] = nullptr;
        ga.bias[0] = inb + Hx;  ga.bias[1] = inb + 2 * Hx;  ga.bias[2] = nullptr;
        ga.C[0] = bufF; ga.C[1] = bufI; ga.C[2] = nullptr;
        ga.lhMask = 0x3;
        hgemm_fused_k<<<gkv, 256, SMEMB>>>(AHp, ALp, ga);
    }

    vecmat_k<<<(Bx * Hx * 32 + 255) / 256, 256>>>(
        bufA + (size_t)(Sx - 1) * Hx, Sx * Hx, inw, inb, nullptr, 0, qP, Bx, Hx);

    scores_k<<<(Bx * NHx * Sx * 32) / 256, 256>>>(qP, bufF, scoresP);
    softmax_k<<<Bx * NHx, 256>>>(scoresP);
    av_k<<<Bx * NHx, 512>>>(scoresP, bufI, oP);

    vecmat_k<<<(Bx * Hx * 32 + 255) / 256, 256>>>(
        oP, Hx, outw, outb, bufA + (size_t)(Sx - 1) * Hx, Sx * Hx, lastP, Bx, Hx);
    vecmat_k<<<(Bx * Ox * 32 + 255) / 256, 256>>>(
        lastP, Hx, fcw, fcb, nullptr, 0, out, Bx, Ox);
}

// round 7
// speedup vs baseline: 4.3470x; 1.1807x over previous
#include <cuda_runtime.h>
#include <cuda_fp16.h>
#include <math.h>
#include <stdint.h>

// Problem constants
#define Bx  16
#define Sx  1024
#define Hx  1024
#define Ox  256
#define Lx  4
#define NHx 8
#define DHx 128
#define Mx  (Bx*Sx)   // 16384 rows
#define CT  32        // scan chunk length
#define CC  (Sx/CT)   // 32 chunks
#define JG  8         // wsum j-split

typedef unsigned long long u64;

// ---------------- scratch (device globals: no allocation allowed) ----------
__device__ float g_bufA[(size_t)Mx * Hx];
__device__ float g_bufF[(size_t)Mx * Hx];
__device__ float g_bufI[(size_t)Mx * Hx];
__device__ float g_bufH[(size_t)Mx * Hx];
__device__ float g_chP[Bx * Hx * CC];
__device__ float g_chQ[Bx * Hx * CC];
__device__ float g_chS[Bx * Hx * CC];
__device__ float g_scores[Bx * NHx * Sx];
__device__ float g_q[Bx * Hx];
__device__ float g_u[Bx * NHx * Hx];           // Wk^T q per (b,head)
__device__ float g_wp[JG * Bx * NHx * Hx];     // partial weighted sums
__device__ float g_w[Bx * NHx * Hx];           // reduced weighted sums
__device__ float g_o[Bx * Hx];
__device__ float g_last[Bx * Hx];

// fp16 hi/lo split buffers (LSTM weights only now)
#define NWF 4194304          // one gate's weights over 4 layers
#define NWTOT (3*NWF)
__device__ __half g_WH[NWTOT];
__device__ __half g_WL[NWTOT];
__device__ __half g_AH[(size_t)Mx * Hx];

// ======================= helpers ===========================================
__device__ __forceinline__ uint32_t smem_u32(const void* p) {
    uint32_t a;
    asm("{ .reg .u64 t; cvta.to.shared.u64 t, %1; cvt.u32.u64 %0, t; }"
        : "=r"(a) : "l"(p));
    return a;
}
__device__ __forceinline__ void cpa16(uint32_t dst, const void* src) {
    asm volatile("cp.async.cg.shared.global [%0], [%1], 16;" :: "r"(dst), "l"(src));
}
__device__ __forceinline__ void ldm4(uint32_t& r0, uint32_t& r1,
                                     uint32_t& r2, uint32_t& r3, uint32_t a) {
    asm volatile("ldmatrix.sync.aligned.m8n8.x4.shared.b16 {%0,%1,%2,%3}, [%4];"
        : "=r"(r0), "=r"(r1), "=r"(r2), "=r"(r3) : "r"(a));
}
__device__ __forceinline__ void mma16816(float* d, const uint32_t* a, const uint32_t* b) {
    asm volatile("mma.sync.aligned.m16n8k16.row.col.f32.f16.f16.f32 "
        "{%0,%1,%2,%3}, {%4,%5,%6,%7}, {%8,%9}, {%0,%1,%2,%3};"
        : "+f"(d[0]), "+f"(d[1]), "+f"(d[2]), "+f"(d[3])
        : "r"(a[0]), "r"(a[1]), "r"(a[2]), "r"(a[3]), "r"(b[0]), "r"(b[1]));
}
__device__ __forceinline__ float fast_rcp(float x) {
    float r; asm("rcp.approx.f32 %0, %1;" : "=f"(r) : "f"(x)); return r;
}

// ======================= fused multi-output HGEMM ==========================
// region = blockIdx.x >> 3 selects (W, bias, C). Products: hh + hl.
struct GemmArgs {
    const __half* WH[3];
    const __half* WL[3];
    const float*  bias[3];
    float*        C[3];
    unsigned      lhMask;
};

#define STG_SZ 32768
#define T_AH 0
#define T_AL 8192
#define T_BH 16384
#define T_BL 24576
#define SMEMB (3 * STG_SZ)

__global__ __launch_bounds__(256) void hgemm_fused_k(
    const __half* __restrict__ AH, const __half* __restrict__ AL, GemmArgs ga)
{
    extern __shared__ __align__(1024) char smem[];
    const uint32_t sb = smem_u32(smem);
    const int tid = threadIdx.x;
    const int wid = tid >> 5, lane = tid & 31;
    const int region = blockIdx.x >> 3;
    const int bx = blockIdx.x & 7;
    const int by = blockIdx.y;
    const bool do_lh = (ga.lhMask >> region) & 1u;

    const __half* WH = ga.WH[region];
    const __half* WL = ga.WL[region];
    const float*  bias = ga.bias[region];
    float*        C = ga.C[region];

    const int lm  = tid >> 1;
    const int lc0 = (tid & 1) * 2;
    const size_t aoff = (size_t)(by * 128 + lm) * Hx;
    const size_t boff = (size_t)(bx * 128 + lm) * Hx;
    const int sws = (lm >> 1) & 3;
    const uint32_t d0 = lm * 64 + 16 * (lc0 ^ sws);
    const uint32_t d1 = lm * 64 + 16 * ((lc0 + 1) ^ sws);
    const int g0 = 8 * lc0, g1 = 8 * (lc0 + 1);

    #define LOAD_CHUNK(k0, s) do {                                          \
        uint32_t st_ = sb + (s) * STG_SZ;                                   \
        cpa16(st_ + T_AH + d0, AH + aoff + (k0) + g0);                      \
        cpa16(st_ + T_AH + d1, AH + aoff + (k0) + g1);                      \
        if (do_lh) {                                                        \
            cpa16(st_ + T_AL + d0, AL + aoff + (k0) + g0);                  \
            cpa16(st_ + T_AL + d1, AL + aoff + (k0) + g1);                  \
        }                                                                   \
        cpa16(st_ + T_BH + d0, WH + boff + (k0) + g0);                      \
        cpa16(st_ + T_BH + d1, WH + boff + (k0) + g1);                      \
        cpa16(st_ + T_BL + d0, WL + boff + (k0) + g0);                      \
        cpa16(st_ + T_BL + d1, WL + boff + (k0) + g1);                      \
        asm volatile("cp.async.commit_group;" ::: "memory");                \
    } while (0)

    const int wm = (wid & 3) * 32;
    const int wn = (wid >> 2) * 64;
    const int ar0 = wm + (lane & 15);
    const int aK  = (lane >> 4) & 1;
    const int bK  = (lane >> 3) & 1;
    const int bnh = (lane >> 4) & 1;
    const int br0 = wn + (lane & 7);

    float acc[2][8][4];
    #pragma unroll
    for (int i = 0; i < 2; i++)
        #pragma unroll
        for (int j = 0; j < 8; j++)
            #pragma unroll
            for (int q = 0; q < 4; q++)
                acc[i][j][q] = 0.f;

    LOAD_CHUNK(0, 0);
    LOAD_CHUNK(32, 1);

    for (int c = 0; c < 32; c++) {
        const int s = c % 3;
        if (c < 31) asm volatile("cp.async.wait_group 1;" ::: "memory");
        else        asm volatile("cp.async.wait_group 0;" ::: "memory");
        __syncthreads();
        if (c + 2 < 32) LOAD_CHUNK((c + 2) * 32, (c + 2) % 3);

        const uint32_t st = sb + s * STG_SZ;
        #pragma unroll
        for (int kk = 0; kk < 2; kk++) {
            uint32_t ah[2][4], al[2][4], bh[8][2], bl[8][2];
            #pragma unroll
            for (int mt = 0; mt < 2; mt++) {
                const int row = ar0 + mt * 16;
                const uint32_t off = (uint32_t)(row * 64
                                   + 16 * ((kk * 2 + aK) ^ ((row >> 1) & 3)));
                ldm4(ah[mt][0], ah[mt][1], ah[mt][2], ah[mt][3], st + T_AH + off);
                if (do_lh)
                    ldm4(al[mt][0], al[mt][1], al[mt][2], al[mt][3], st + T_AL + off);
            }
            #pragma unroll
            for (int p = 0; p < 4; p++) {
                const int row = br0 + (p * 2 + bnh) * 8;
                const uint32_t off = (uint32_t)(row * 64
                                   + 16 * ((kk * 2 + bK) ^ ((row >> 1) & 3)));
                ldm4(bh[2*p][0], bh[2*p][1], bh[2*p+1][0], bh[2*p+1][1], st + T_BH + off);
                ldm4(bl[2*p][0], bl[2*p][1], bl[2*p+1][0], bl[2*p+1][1], st + T_BL + off);
            }
            #pragma unroll
            for (int mt = 0; mt < 2; mt++)
                #pragma unroll
                for (int nt = 0; nt < 8; nt++)
                    mma16816(acc[mt][nt], ah[mt], bh[nt]);
            #pragma unroll
            for (int mt = 0; mt < 2; mt++)
                #pragma unroll
                for (int nt = 0; nt < 8; nt++)
                    mma16816(acc[mt][nt], ah[mt], bl[nt]);
            if (do_lh) {
                #pragma unroll
                for (int mt = 0; mt < 2; mt++)
                    #pragma unroll
                    for (int nt = 0; nt < 8; nt++)
                        mma16816(acc[mt][nt], al[mt], bh[nt]);
            }
        }
    }

    const int r0 = lane >> 2;
    const int cc = (lane & 3) * 2;
    #pragma unroll
    for (int mt = 0; mt < 2; mt++) {
        const int mrow = by * 128 + wm + mt * 16 + r0;
        #pragma unroll
        for (int nt = 0; nt < 8; nt++) {
            const int col = bx * 128 + wn + nt * 8 + cc;
            const float b0 = bias[col], b1 = bias[col + 1];
            float2 v0 = {acc[mt][nt][0] + b0, acc[mt][nt][1] + b1};
            float2 v1 = {acc[mt][nt][2] + b0, acc[mt][nt][3] + b1};
            *(float2*)&C[(size_t)mrow * Hx + col]       = v0;
            *(float2*)&C[(size_t)(mrow + 8) * Hx + col] = v1;
        }
    }
}

// ---------------- fp32 -> f16 hi(/lo) conversion ---------------------------
__global__ __launch_bounds__(256) void conv_k(
    const float* __restrict__ src, __half* __restrict__ hi,
    __half* __restrict__ lo, int n, int writeLo)
{
    int i = blockIdx.x * blockDim.x + threadIdx.x;
    if (i >= n / 4) return;
    float4 v = ((const float4*)src)[i];
    __half h0 = __float2half_rn(v.x), h1 = __float2half_rn(v.y);
    __half h2 = __float2half_rn(v.z), h3 = __float2half_rn(v.w);
    __half2* hp = (__half2*)hi;
    hp[i * 2]     = __halves2half2(h0, h1);
    hp[i * 2 + 1] = __halves2half2(h2, h3);
    if (writeLo) {
        __half l0 = __float2half_rn(v.x - __half2float(h0));
        __half l1 = __float2half_rn(v.y - __half2float(h1));
        __half l2 = __float2half_rn(v.z - __half2float(h2));
        __half l3 = __float2half_rn(v.w - __half2float(h3));
        __half2* lp = (__half2*)lo;
        lp[i * 2]     = __halves2half2(l0, l1);
        lp[i * 2 + 1] = __halves2half2(l2, l3);
    }
}

// ---------------- chunked minLSTM scan -------------------------------------
__global__ __launch_bounds__(256) void scan_p1(
    const float* __restrict__ F, const float* __restrict__ I,
    const float* __restrict__ Ht, float* __restrict__ P, float* __restrict__ Q,
    float* __restrict__ chP, float* __restrict__ chQ)
{
    int t = blockIdx.x * blockDim.x + threadIdx.x;
    int h = t & (Hx - 1);
    int bc = t >> 10;
    int c = bc & (CC - 1);
    int b = bc >> 5;
    size_t base = ((size_t)b * Sx + (size_t)c * CT) * Hx + h;
    float accP = 1.f, accQ = 0.f;
    #pragma unroll 4
    for (int s = 0; s < CT; s++) {
        size_t idx = base + (size_t)s * Hx;
        float ea = __expf(F[idx]);
        float eb = __expf(I[idx]);
        float hv = Ht[idx];
        float na = ea * (1.f + eb);
        float nb = eb * (1.f + ea);
        float r = fast_rcp(na + nb);
        float p = na * r;
        float q = nb * r * hv;
        P[idx] = p; Q[idx] = q;
        accQ = fmaf(p, accQ, q);
        accP *= p;
    }
    chP[t] = accP;
    chQ[t] = accQ;
}

__global__ __launch_bounds__(256) void scan_p2(
    const float* __restrict__ chP, const float* __restrict__ chQ,
    float* __restrict__ chS)
{
    int u = blockIdx.x * blockDim.x + threadIdx.x;
    int h = u & (Hx - 1);
    int b = u >> 10;
    float hc = 0.f;
    #pragma unroll
    for (int c = 0; c < CC; c++) {
        size_t idx = ((size_t)b * CC + c) * Hx + h;
        chS[idx] = hc;
        hc = fmaf(chP[idx], hc, chQ[idx]);
    }
}

// pass3: apply scan. writeOut -> fp32 Out (last layer, attention needs it),
// writeAH -> f16 hi (feeds the next layer's GEMM).
__global__ __launch_bounds__(256) void scan_p3(
    const float* __restrict__ P, const float* __restrict__ Q,
    const float* __restrict__ chS, float* __restrict__ Out,
    __half* __restrict__ OH, int writeOut, int writeAH)
{
    int t = blockIdx.x * blockDim.x + threadIdx.x;
    int h = t & (Hx - 1);
    int bc = t >> 10;
    int c = bc & (CC - 1);
    int b = bc >> 5;
    size_t base = ((size_t)b * Sx + (size_t)c * CT) * Hx + h;
    float hp = chS[t];
    #pragma unroll 4
    for (int s = 0; s < CT; s++) {
        size_t idx = base + (size_t)s * Hx;
        hp = fmaf(P[idx], hp, Q[idx]);
        if (writeOut) Out[idx] = hp;
        if (writeAH)  OH[idx] = __float2half_rn(hp);
    }
}

// ---------------- small vec-mat --------------------------------------------
__global__ void vecmat_k(const float* __restrict__ X, int xStride,
                         const float* __restrict__ W, const float* __restrict__ bias,
                         const float* __restrict__ res, int resStride,
                         float* __restrict__ out, int Bn, int N)
{
    int gw = (blockIdx.x * blockDim.x + threadIdx.x) >> 5;
    int lane = threadIdx.x & 31;
    if (gw >= Bn * N) return;
    int b = gw / N, n = gw % N;
    const float* xr = X + (size_t)b * xStride;
    const float* wr = W + (size_t)n * Hx;
    float s = 0.f;
    #pragma unroll
    for (int k = lane * 4; k < Hx; k += 128) {
        float4 xv = *(const float4*)(xr + k);
        float4 wv = *(const float4*)(wr + k);
        s += xv.x * wv.x + xv.y * wv.y + xv.z * wv.z + xv.w * wv.w;
    }
    #pragma unroll
    for (int o = 16; o; o >>= 1) s += __shfl_xor_sync(0xffffffffu, s, o);
    if (lane == 0) {
        float v = s + bias[n];
        if (res) v += res[(size_t)b * resStride + n];
        out[(size_t)b * N + n] = v;
    }
}

// ---------------- attention via projection pullback ------------------------
// u[b,n,:] = sum_hd q[b,n*128+hd] * Wk[n*128+hd,:]   (Wk = inw rows Hx..2Hx)
__global__ __launch_bounds__(256) void ku_k(
    const float* __restrict__ q, const float* __restrict__ inw,
    float* __restrict__ u)
{
    int bn = blockIdx.x;           // b*8+n
    int n = bn & (NHx - 1), b = bn >> 3;
    __shared__ float qs[DHx];
    if (threadIdx.x < DHx) qs[threadIdx.x] = q[(size_t)b * Hx + n * DHx + threadIdx.x];
    __syncthreads();
    const float* Wk = inw + ((size_t)Hx + (size_t)n * DHx) * Hx;
    #pragma unroll
    for (int m0 = 0; m0 < Hx; m0 += 256) {
        int m = m0 + threadIdx.x;
        float acc = 0.f;
        #pragma unroll 8
        for (int hd = 0; hd < DHx; hd++)
            acc = fmaf(qs[hd], Wk[(size_t)hd * Hx + m], acc);
        u[(size_t)bn * Hx + m] = acc;
    }
}

// scores[b,n,j] = (x[b,j,:] . u[b,n,:]) / sqrt(dh)
__global__ __launch_bounds__(256) void scores2_k(
    const float* __restrict__ X, const float* __restrict__ u,
    float* __restrict__ sc)
{
    int b = blockIdx.x >> 4;
    int jt = blockIdx.x & 15;      // j-tile of 64
    __shared__ float us[NHx][Hx];  // 32KB
    for (int i = threadIdx.x; i < NHx * Hx; i += 256)
        us[i >> 10][i & (Hx - 1)] = u[(size_t)b * NHx * Hx + i];
    __syncthreads();
    int wid = threadIdx.x >> 5, lane = threadIdx.x & 31;
    #pragma unroll
    for (int jj = 0; jj < 8; jj++) {
        int j = jt * 64 + wid * 8 + jj;
        const float4* xr = (const float4*)(X + ((size_t)b * Sx + j) * Hx);
        float acc[NHx] = {0.f, 0.f, 0.f, 0.f, 0.f, 0.f, 0.f, 0.f};
        for (int k = lane; k < Hx / 4; k += 32) {
            float4 xv = xr[k];
            #pragma unroll
            for (int n = 0; n < NHx; n++) {
                float4 uv = *(const float4*)&us[n][k * 4];
                acc[n] += xv.x * uv.x + xv.y * uv.y + xv.z * uv.z + xv.w * uv.w;
            }
        }
        #pragma unroll
        for (int n = 0; n < NHx; n++) {
            float s = acc[n];
            #pragma unroll
            for (int o = 16; o; o >>= 1) s += __shfl_xor_sync(0xffffffffu, s, o);
            if (lane == 0)
                sc[((size_t)(b * NHx + n)) * Sx + j] = s * 0.0883883476483184f;
        }
    }
}

__global__ __launch_bounds__(256) void softmax_k(float* __restrict__ sc)
{
    int row = blockIdx.x;
    float4* p = (float4*)(sc + (size_t)row * Sx);
    int t = threadIdx.x;
    float4 v = p[t];
    __shared__ float sh[8];

    float m = fmaxf(fmaxf(v.x, v.y), fmaxf(v.z, v.w));
    #pragma unroll
    for (int o = 16; o; o >>= 1) m = fmaxf(m, __shfl_xor_sync(0xffffffffu, m, o));
    if ((t & 31) == 0) sh[t >> 5] = m;
    __syncthreads();
    m = sh[0];
    #pragma unroll
    for (int i = 1; i < 8; i++) m = fmaxf(m, sh[i]);

    v.x = __expf(v.x - m); v.y = __expf(v.y - m);
    v.z = __expf(v.z - m); v.w = __expf(v.w - m);
    float sum = v.x + v.y + v.z + v.w;
    #pragma unroll
    for (int o = 16; o; o >>= 1) sum += __shfl_xor_sync(0xffffffffu, sum, o);
    __syncthreads();
    if ((t & 31) == 0) sh[t >> 5] = sum;
    __syncthreads();
    sum = 0.f;
    #pragma unroll
    for (int i = 0; i < 8; i++) sum += sh[i];
    float inv = 1.f / sum;
    v.x *= inv; v.y *= inv; v.z *= inv; v.w *= inv;
    p[t] = v;
}

// partial weighted sums: wp[jg][b][n][m] = sum_{j in jg-range} a[b,n,j]*x[b,j,m]
__global__ __launch_bounds__(128) void wsum_k(
    const float* __restrict__ X, const float* __restrict__ sc,
    float* __restrict__ wp)
{
    int b = blockIdx.x, mt = blockIdx.y, jg = blockIdx.z;
    int m = mt * 128 + threadIdx.x;
    __shared__ float as[NHx][128];
    for (int i = threadIdx.x; i < NHx * 128; i += 128)
        as[i >> 7][i & 127] =
            sc[((size_t)(b * NHx + (i >> 7))) * Sx + jg * 128 + (i & 127)];
    __syncthreads();
    float acc[NHx] = {0.f, 0.f, 0.f, 0.f, 0.f, 0.f, 0.f, 0.f};
    const float* xp = X + ((size_t)b * Sx + jg * 128) * Hx + m;
    #pragma unroll 4
    for (int jj = 0; jj < 128; jj++) {
        float xv = xp[(size_t)jj * Hx];
        #pragma unroll
        for (int n = 0; n < NHx; n++) acc[n] = fmaf(as[n][jj], xv, acc[n]);
    }
    #pragma unroll
    for (int n = 0; n < NHx; n++)
        wp[(((size_t)jg * Bx + b) * NHx + n) * Hx + m] = acc[n];
}

// reduce partials
__global__ void wred_k(const float* __restrict__ wp, float* __restrict__ w)
{
    int i = blockIdx.x * blockDim.x + threadIdx.x;  // < Bx*NHx*Hx
    float s = 0.f;
    #pragma unroll
    for (int jg = 0; jg < JG; jg++)
        s += wp[(size_t)jg * (Bx * NHx * Hx) + i];
    w[i] = s;
}

// o[b, hd] = Wv[hd,:] . w[b, hd>>7, :] + bv[hd]   (Wv = inw rows 2Hx..3Hx)
__global__ void ov_k(const float* __restrict__ w, const float* __restrict__ inw,
                     const float* __restrict__ inb, float* __restrict__ o)
{
    int gw = (blockIdx.x * blockDim.x + threadIdx.x) >> 5;
    int lane = threadIdx.x & 31;
    if (gw >= Bx * Hx) return;
    int hd = gw & (Hx - 1), b = gw >> 10;
    int n = hd >> 7;
    const float4* wr = (const float4*)(w + ((size_t)(b * NHx + n)) * Hx);
    const float4* vr = (const float4*)(inw + ((size_t)(2 * Hx + hd)) * Hx);
    float s = 0.f;
    #pragma unroll
    for (int k = lane; k < Hx / 4; k += 32) {
        float4 a = wr[k], c = vr[k];
        s += a.x * c.x + a.y * c.y + a.z * c.z + a.w * c.w;
    }
    #pragma unroll
    for (int o2 = 16; o2; o2 >>= 1) s += __shfl_xor_sync(0xffffffffu, s, o2);
    if (lane == 0) o[(size_t)b * Hx + hd] = s + inb[2 * Hx + hd];
}

// ---------------- launch orchestration -------------------------------------
extern "C" void kernel_launch(void* const* d_in, const int* in_sizes, int n_in,
                              void* d_out, int out_size)
{
    const float* x    = (const float*)d_in[0];
    const float* Wf   = (const float*)d_in[1];
    const float* bf   = (const float*)d_in[2];
    const float* Wi   = (const float*)d_in[3];
    const float* bi   = (const float*)d_in[4];
    const float* Wh   = (const float*)d_in[5];
    const float* bh   = (const float*)d_in[6];
    const float* inw  = (const float*)d_in[7];
    const float* inb  = (const float*)d_in[8];
    const float* outw = (const float*)d_in[9];
    const float* outb = (const float*)d_in[10];
    const float* fcw  = (const float*)d_in[11];
    const float* fcb  = (const float*)d_in[12];
    float* out = (float*)d_out;

    float *bufA, *bufF, *bufI, *bufH, *chP, *chQ, *chS;
    float *scoresP, *qP, *uP, *wpP, *wP, *oP, *lastP;
    __half *WHp, *WLp, *AHp;
    cudaGetSymbolAddress((void**)&bufA, g_bufA);
    cudaGetSymbolAddress((void**)&bufF, g_bufF);
    cudaGetSymbolAddress((void**)&bufI, g_bufI);
    cudaGetSymbolAddress((void**)&bufH, g_bufH);
    cudaGetSymbolAddress((void**)&chP, g_chP);
    cudaGetSymbolAddress((void**)&chQ, g_chQ);
    cudaGetSymbolAddress((void**)&chS, g_chS);
    cudaGetSymbolAddress((void**)&scoresP, g_scores);
    cudaGetSymbolAddress((void**)&qP, g_q);
    cudaGetSymbolAddress((void**)&uP, g_u);
    cudaGetSymbolAddress((void**)&wpP, g_wp);
    cudaGetSymbolAddress((void**)&wP, g_w);
    cudaGetSymbolAddress((void**)&oP, g_o);
    cudaGetSymbolAddress((void**)&lastP, g_last);
    cudaGetSymbolAddress((void**)&WHp, g_WH);
    cudaGetSymbolAddress((void**)&WLp, g_WL);
    cudaGetSymbolAddress((void**)&AHp, g_AH);

    static int smemSet = 0;
    if (!smemSet) {
        cudaFuncSetAttribute(hgemm_fused_k,
                             cudaFuncAttributeMaxDynamicSharedMemorySize, SMEMB);
        smemSet = 1;
    }

    // ---- conversions: LSTM weights hi/lo + layer-0 activations (hi only)
    conv_k<<<NWF / 4 / 256, 256>>>(Wf, WHp,           WLp,           NWF, 1);
    conv_k<<<NWF / 4 / 256, 256>>>(Wi, WHp + NWF,     WLp + NWF,     NWF, 1);
    conv_k<<<NWF / 4 / 256, 256>>>(Wh, WHp + 2 * NWF, WLp + 2 * NWF, NWF, 1);
    conv_k<<<(Mx * Hx) / 4 / 256, 256>>>(x, AHp, nullptr, Mx * Hx, 0);

    dim3 gl(24, 128);                 // fused f,i,h GEMM
    const int scanT = Bx * CC * Hx;   // 512K threads

    for (int l = 0; l < Lx; l++) {
        size_t wo = (size_t)l * Hx * Hx;
        GemmArgs ga;
        ga.WH[0] = WHp + wo;           ga.WL[0] = WLp + wo;
        ga.WH[1] = WHp + NWF + wo;     ga.WL[1] = WLp + NWF + wo;
        ga.WH[2] = WHp + 2 * NWF + wo; ga.WL[2] = WLp + 2 * NWF + wo;
        ga.bias[0] = bf + (size_t)l * Hx;
        ga.bias[1] = bi + (size_t)l * Hx;
        ga.bias[2] = bh + (size_t)l * Hx;
        ga.C[0] = bufF; ga.C[1] = bufI; ga.C[2] = bufH;
        ga.lhMask = 0x0;
        hgemm_fused_k<<<gl, 256, SMEMB>>>(AHp, AHp, ga);
        scan_p1<<<scanT / 256, 256>>>(bufF, bufI, bufH, bufF, bufI, chP, chQ);
        scan_p2<<<(Bx * Hx) / 256, 256>>>(chP, chQ, chS);
        scan_p3<<<scanT / 256, 256>>>(bufF, bufI, chS, bufA, AHp,
                                      (l == Lx - 1) ? 1 : 0,
                                      (l == Lx - 1) ? 0 : 1);
    }

    // ---- attention on last query row via pullback (exact fp32, no KV GEMM)
    vecmat_k<<<(Bx * Hx * 32 + 255) / 256, 256>>>(
        bufA + (size_t)(Sx - 1) * Hx, Sx * Hx, inw, inb, nullptr, 0, qP, Bx, Hx);
    ku_k<<<Bx * NHx, 256>>>(qP, inw, uP);
    scores2_k<<<Bx * 16, 256>>>(bufA, uP, scoresP);
    softmax_k<<<Bx * NHx, 256>>>(scoresP);
    wsum_k<<<dim3(Bx, 8, JG), 128>>>(bufA, scoresP, wpP);
    wred_k<<<(Bx * NHx * Hx) / 256, 256>>>(wpP, wP);
    ov_k<<<(Bx * Hx * 32 + 255) / 256, 256>>>(wP, inw, inb, oP);

    // ---- out-proj + residual (last token), then fc head
    vecmat_k<<<(Bx * Hx * 32 + 255) / 256, 256>>>(
        oP, Hx, outw, outb, bufA + (size_t)(Sx - 1) * Hx, Sx * Hx, lastP, Bx, Hx);
    vecmat_k<<<(Bx * Ox * 32 + 255) / 256, 256>>>(
        lastP, Hx, fcw, fcb, nullptr, 0, out, Bx, Ox);
}

// round 8
// speedup vs baseline: 5.3006x; 1.2193x over previous
#include <cuda_runtime.h>
#include <cuda_fp16.h>
#include <math.h>
#include <stdint.h>

// Problem constants
#define Bx  16
#define Sx  1024
#define Hx  1024
#define Ox  256
#define Lx  4
#define NHx 8
#define DHx 128
#define Mx  (Bx*Sx)   // 16384 rows
#define CT  32        // scan chunk length
#define CC  (Sx/CT)   // 32 chunks
#define JG  8         // wsum j-split

typedef unsigned long long u64;

// ---------------- scratch (device globals: no allocation allowed) ----------
__device__ float g_bufA[(size_t)Mx * Hx];
__device__ float g_bufF[(size_t)Mx * Hx];
__device__ float g_bufI[(size_t)Mx * Hx];
__device__ float g_bufH[(size_t)Mx * Hx];
__device__ float g_chP[Bx * Hx * CC];
__device__ float g_chQ[Bx * Hx * CC];
__device__ float g_chS[Bx * Hx * CC];
__device__ float g_scores[Bx * NHx * Sx];
__device__ float g_q[Bx * Hx];
__device__ float g_u[Bx * NHx * Hx];           // Wk^T q per (b,head)
__device__ float g_wp[JG * Bx * NHx * Hx];     // partial weighted sums
__device__ float g_w[Bx * NHx * Hx];           // reduced weighted sums
__device__ float g_o[Bx * Hx];
__device__ float g_last[Bx * Hx];

// fp16 hi/lo split buffers (LSTM weights only)
#define NWF 4194304          // one gate's weights over 4 layers
#define NWTOT (3*NWF)
__device__ __half g_WH[NWTOT];
__device__ __half g_WL[NWTOT];   // only h~ slice used now
__device__ __half g_AH[(size_t)Mx * Hx];

// ======================= helpers ===========================================
__device__ __forceinline__ uint32_t smem_u32(const void* p) {
    uint32_t a;
    asm("{ .reg .u64 t; cvta.to.shared.u64 t, %1; cvt.u32.u64 %0, t; }"
        : "=r"(a) : "l"(p));
    return a;
}
__device__ __forceinline__ void cpa16(uint32_t dst, const void* src) {
    asm volatile("cp.async.cg.shared.global [%0], [%1], 16;" :: "r"(dst), "l"(src));
}
__device__ __forceinline__ void ldm4(uint32_t& r0, uint32_t& r1,
                                     uint32_t& r2, uint32_t& r3, uint32_t a) {
    asm volatile("ldmatrix.sync.aligned.m8n8.x4.shared.b16 {%0,%1,%2,%3}, [%4];"
        : "=r"(r0), "=r"(r1), "=r"(r2), "=r"(r3) : "r"(a));
}
__device__ __forceinline__ void mma16816(float* d, const uint32_t* a, const uint32_t* b) {
    asm volatile("mma.sync.aligned.m16n8k16.row.col.f32.f16.f16.f32 "
        "{%0,%1,%2,%3}, {%4,%5,%6,%7}, {%8,%9}, {%0,%1,%2,%3};"
        : "+f"(d[0]), "+f"(d[1]), "+f"(d[2]), "+f"(d[3])
        : "r"(a[0]), "r"(a[1]), "r"(a[2]), "r"(a[3]), "r"(b[0]), "r"(b[1]));
}
__device__ __forceinline__ float fast_rcp(float x) {
    float r; asm("rcp.approx.f32 %0, %1;" : "=f"(r) : "f"(x)); return r;
}

// ======================= fused multi-output HGEMM ==========================
// region = blockIdx.x >> 3 selects (W, bias, C).
// Per-region products: hh always; + hl iff (hlMask>>region)&1;
//                      + lh iff (lhMask>>region)&1.
struct GemmArgs {
    const __half* WH[3];
    const __half* WL[3];
    const float*  bias[3];
    float*        C[3];
    unsigned      hlMask;
    unsigned      lhMask;
};

#define STG_SZ 32768
#define T_AH 0
#define T_AL 8192
#define T_BH 16384
#define T_BL 24576
#define SMEMB (3 * STG_SZ)

__global__ __launch_bounds__(256) void hgemm_fused_k(
    const __half* __restrict__ AH, const __half* __restrict__ AL, GemmArgs ga)
{
    extern __shared__ __align__(1024) char smem[];
    const uint32_t sb = smem_u32(smem);
    const int tid = threadIdx.x;
    const int wid = tid >> 5, lane = tid & 31;
    const int region = blockIdx.x >> 3;
    const int bx = blockIdx.x & 7;
    const int by = blockIdx.y;
    const bool do_hl = (ga.hlMask >> region) & 1u;
    const bool do_lh = (ga.lhMask >> region) & 1u;

    const __half* WH = ga.WH[region];
    const __half* WL = ga.WL[region];
    const float*  bias = ga.bias[region];
    float*        C = ga.C[region];

    const int lm  = tid >> 1;
    const int lc0 = (tid & 1) * 2;
    const size_t aoff = (size_t)(by * 128 + lm) * Hx;
    const size_t boff = (size_t)(bx * 128 + lm) * Hx;
    const int sws = (lm >> 1) & 3;
    const uint32_t d0 = lm * 64 + 16 * (lc0 ^ sws);
    const uint32_t d1 = lm * 64 + 16 * ((lc0 + 1) ^ sws);
    const int g0 = 8 * lc0, g1 = 8 * (lc0 + 1);

    #define LOAD_CHUNK(k0, s) do {                                          \
        uint32_t st_ = sb + (s) * STG_SZ;                                   \
        cpa16(st_ + T_AH + d0, AH + aoff + (k0) + g0);                      \
        cpa16(st_ + T_AH + d1, AH + aoff + (k0) + g1);                      \
        if (do_lh) {                                                        \
            cpa16(st_ + T_AL + d0, AL + aoff + (k0) + g0);                  \
            cpa16(st_ + T_AL + d1, AL + aoff + (k0) + g1);                  \
        }                                                                   \
        cpa16(st_ + T_BH + d0, WH + boff + (k0) + g0);                      \
        cpa16(st_ + T_BH + d1, WH + boff + (k0) + g1);                      \
        if (do_hl) {                                                        \
            cpa16(st_ + T_BL + d0, WL + boff + (k0) + g0);                  \
            cpa16(st_ + T_BL + d1, WL + boff + (k0) + g1);                  \
        }                                                                   \
        asm volatile("cp.async.commit_group;" ::: "memory");                \
    } while (0)

    const int wm = (wid & 3) * 32;
    const int wn = (wid >> 2) * 64;
    const int ar0 = wm + (lane & 15);
    const int aK  = (lane >> 4) & 1;
    const int bK  = (lane >> 3) & 1;
    const int bnh = (lane >> 4) & 1;
    const int br0 = wn + (lane & 7);

    float acc[2][8][4];
    #pragma unroll
    for (int i = 0; i < 2; i++)
        #pragma unroll
        for (int j = 0; j < 8; j++)
            #pragma unroll
            for (int q = 0; q < 4; q++)
                acc[i][j][q] = 0.f;

    LOAD_CHUNK(0, 0);
    LOAD_CHUNK(32, 1);

    for (int c = 0; c < 32; c++) {
        const int s = c % 3;
        if (c < 31) asm volatile("cp.async.wait_group 1;" ::: "memory");
        else        asm volatile("cp.async.wait_group 0;" ::: "memory");
        __syncthreads();
        if (c + 2 < 32) LOAD_CHUNK((c + 2) * 32, (c + 2) % 3);

        const uint32_t st = sb + s * STG_SZ;
        #pragma unroll
        for (int kk = 0; kk < 2; kk++) {
            uint32_t ah[2][4], al[2][4], bh[8][2], bl[8][2];
            #pragma unroll
            for (int mt = 0; mt < 2; mt++) {
                const int row = ar0 + mt * 16;
                const uint32_t off = (uint32_t)(row * 64
                                   + 16 * ((kk * 2 + aK) ^ ((row >> 1) & 3)));
                ldm4(ah[mt][0], ah[mt][1], ah[mt][2], ah[mt][3], st + T_AH + off);
                if (do_lh)
                    ldm4(al[mt][0], al[mt][1], al[mt][2], al[mt][3], st + T_AL + off);
            }
            #pragma unroll
            for (int p = 0; p < 4; p++) {
                const int row = br0 + (p * 2 + bnh) * 8;
                const uint32_t off = (uint32_t)(row * 64
                                   + 16 * ((kk * 2 + bK) ^ ((row >> 1) & 3)));
                ldm4(bh[2*p][0], bh[2*p][1], bh[2*p+1][0], bh[2*p+1][1], st + T_BH + off);
                if (do_hl)
                    ldm4(bl[2*p][0], bl[2*p][1], bl[2*p+1][0], bl[2*p+1][1], st + T_BL + off);
            }
            // product 1: hi*hi (always)
            #pragma unroll
            for (int mt = 0; mt < 2; mt++)
                #pragma unroll
                for (int nt = 0; nt < 8; nt++)
                    mma16816(acc[mt][nt], ah[mt], bh[nt]);
            // product 2: hi*lo
            if (do_hl) {
                #pragma unroll
                for (int mt = 0; mt < 2; mt++)
                    #pragma unroll
                    for (int nt = 0; nt < 8; nt++)
                        mma16816(acc[mt][nt], ah[mt], bl[nt]);
            }
            // product 3: lo*hi
            if (do_lh) {
                #pragma unroll
                for (int mt = 0; mt < 2; mt++)
                    #pragma unroll
                    for (int nt = 0; nt < 8; nt++)
                        mma16816(acc[mt][nt], al[mt], bh[nt]);
            }
        }
    }

    const int r0 = lane >> 2;
    const int cc = (lane & 3) * 2;
    #pragma unroll
    for (int mt = 0; mt < 2; mt++) {
        const int mrow = by * 128 + wm + mt * 16 + r0;
        #pragma unroll
        for (int nt = 0; nt < 8; nt++) {
            const int col = bx * 128 + wn + nt * 8 + cc;
            const float b0 = bias[col], b1 = bias[col + 1];
            float2 v0 = {acc[mt][nt][0] + b0, acc[mt][nt][1] + b1};
            float2 v1 = {acc[mt][nt][2] + b0, acc[mt][nt][3] + b1};
            *(float2*)&C[(size_t)mrow * Hx + col]       = v0;
            *(float2*)&C[(size_t)(mrow + 8) * Hx + col] = v1;
        }
    }
}

// ---------------- fp32 -> f16 hi(/lo) conversion ---------------------------
__global__ __launch_bounds__(256) void conv_k(
    const float* __restrict__ src, __half* __restrict__ hi,
    __half* __restrict__ lo, int n, int writeLo)
{
    int i = blockIdx.x * blockDim.x + threadIdx.x;
    if (i >= n / 4) return;
    float4 v = ((const float4*)src)[i];
    __half h0 = __float2half_rn(v.x), h1 = __float2half_rn(v.y);
    __half h2 = __float2half_rn(v.z), h3 = __float2half_rn(v.w);
    __half2* hp = (__half2*)hi;
    hp[i * 2]     = __halves2half2(h0, h1);
    hp[i * 2 + 1] = __halves2half2(h2, h3);
    if (writeLo) {
        __half l0 = __float2half_rn(v.x - __half2float(h0));
        __half l1 = __float2half_rn(v.y - __half2float(h1));
        __half l2 = __float2half_rn(v.z - __half2float(h2));
        __half l3 = __float2half_rn(v.w - __half2float(h3));
        __half2* lp = (__half2*)lo;
        lp[i * 2]     = __halves2half2(l0, l1);
        lp[i * 2 + 1] = __halves2half2(l2, l3);
    }
}

// ---------------- chunked minLSTM scan -------------------------------------
__global__ __launch_bounds__(256) void scan_p1(
    const float* __restrict__ F, const float* __restrict__ I,
    const float* __restrict__ Ht, float* __restrict__ P, float* __restrict__ Q,
    float* __restrict__ chP, float* __restrict__ chQ)
{
    int t = blockIdx.x * blockDim.x + threadIdx.x;
    int h = t & (Hx - 1);
    int bc = t >> 10;
    int c = bc & (CC - 1);
    int b = bc >> 5;
    size_t base = ((size_t)b * Sx + (size_t)c * CT) * Hx + h;
    float accP = 1.f, accQ = 0.f;
    #pragma unroll 4
    for (int s = 0; s < CT; s++) {
        size_t idx = base + (size_t)s * Hx;
        float ea = __expf(F[idx]);
        float eb = __expf(I[idx]);
        float hv = Ht[idx];
        float na = ea * (1.f + eb);
        float nb = eb * (1.f + ea);
        float r = fast_rcp(na + nb);
        float p = na * r;
        float q = nb * r * hv;
        P[idx] = p; Q[idx] = q;
        accQ = fmaf(p, accQ, q);
        accP *= p;
    }
    chP[t] = accP;
    chQ[t] = accQ;
}

__global__ __launch_bounds__(256) void scan_p2(
    const float* __restrict__ chP, const float* __restrict__ chQ,
    float* __restrict__ chS)
{
    int u = blockIdx.x * blockDim.x + threadIdx.x;
    int h = u & (Hx - 1);
    int b = u >> 10;
    float hc = 0.f;
    #pragma unroll
    for (int c = 0; c < CC; c++) {
        size_t idx = ((size_t)b * CC + c) * Hx + h;
        chS[idx] = hc;
        hc = fmaf(chP[idx], hc, chQ[idx]);
    }
}

// pass3: apply scan. writeOut -> fp32 Out (last layer only),
// writeAH -> f16 hi (feeds next layer's GEMM).
__global__ __launch_bounds__(256) void scan_p3(
    const float* __restrict__ P, const float* __restrict__ Q,
    const float* __restrict__ chS, float* __restrict__ Out,
    __half* __restrict__ OH, int writeOut, int writeAH)
{
    int t = blockIdx.x * blockDim.x + threadIdx.x;
    int h = t & (Hx - 1);
    int bc = t >> 10;
    int c = bc & (CC - 1);
    int b = bc >> 5;
    size_t base = ((size_t)b * Sx + (size_t)c * CT) * Hx + h;
    float hp = chS[t];
    #pragma unroll 4
    for (int s = 0; s < CT; s++) {
        size_t idx = base + (size_t)s * Hx;
        hp = fmaf(P[idx], hp, Q[idx]);
        if (writeOut) Out[idx] = hp;
        if (writeAH)  OH[idx] = __float2half_rn(hp);
    }
}

// ---------------- small vec-mat --------------------------------------------
__global__ void vecmat_k(const float* __restrict__ X, int xStride,
                         const float* __restrict__ W, const float* __restrict__ bias,
                         const float* __restrict__ res, int resStride,
                         float* __restrict__ out, int Bn, int N)
{
    int gw = (blockIdx.x * blockDim.x + threadIdx.x) >> 5;
    int lane = threadIdx.x & 31;
    if (gw >= Bn * N) return;
    int b = gw / N, n = gw % N;
    const float* xr = X + (size_t)b * xStride;
    const float* wr = W + (size_t)n * Hx;
    float s = 0.f;
    #pragma unroll
    for (int k = lane * 4; k < Hx; k += 128) {
        float4 xv = *(const float4*)(xr + k);
        float4 wv = *(const float4*)(wr + k);
        s += xv.x * wv.x + xv.y * wv.y + xv.z * wv.z + xv.w * wv.w;
    }
    #pragma unroll
    for (int o = 16; o; o >>= 1) s += __shfl_xor_sync(0xffffffffu, s, o);
    if (lane == 0) {
        float v = s + bias[n];
        if (res) v += res[(size_t)b * resStride + n];
        out[(size_t)b * N + n] = v;
    }
}

// ---------------- attention via projection pullback ------------------------
__global__ __launch_bounds__(256) void ku_k(
    const float* __restrict__ q, const float* __restrict__ inw,
    float* __restrict__ u)
{
    int bn = blockIdx.x;           // b*8+n
    int n = bn & (NHx - 1), b = bn >> 3;
    __shared__ float qs[DHx];
    if (threadIdx.x < DHx) qs[threadIdx.x] = q[(size_t)b * Hx + n * DHx + threadIdx.x];
    __syncthreads();
    const float* Wk = inw + ((size_t)Hx + (size_t)n * DHx) * Hx;
    #pragma unroll
    for (int m0 = 0; m0 < Hx; m0 += 256) {
        int m = m0 + threadIdx.x;
        float acc = 0.f;
        #pragma unroll 8
        for (int hd = 0; hd < DHx; hd++)
            acc = fmaf(qs[hd], Wk[(size_t)hd * Hx + m], acc);
        u[(size_t)bn * Hx + m] = acc;
    }
}

__global__ __launch_bounds__(256) void scores2_k(
    const float* __restrict__ X, const float* __restrict__ u,
    float* __restrict__ sc)
{
    int b = blockIdx.x >> 4;
    int jt = blockIdx.x & 15;      // j-tile of 64
    __shared__ float us[NHx][Hx];  // 32KB
    for (int i = threadIdx.x; i < NHx * Hx; i += 256)
        us[i >> 10][i & (Hx - 1)] = u[(size_t)b * NHx * Hx + i];
    __syncthreads();
    int wid = threadIdx.x >> 5, lane = threadIdx.x & 31;
    #pragma unroll
    for (int jj = 0; jj < 8; jj++) {
        int j = jt * 64 + wid * 8 + jj;
        const float4* xr = (const float4*)(X + ((size_t)b * Sx + j) * Hx);
        float acc[NHx] = {0.f, 0.f, 0.f, 0.f, 0.f, 0.f, 0.f, 0.f};
        for (int k = lane; k < Hx / 4; k += 32) {
            float4 xv = xr[k];
            #pragma unroll
            for (int n = 0; n < NHx; n++) {
                float4 uv = *(const float4*)&us[n][k * 4];
                acc[n] += xv.x * uv.x + xv.y * uv.y + xv.z * uv.z + xv.w * uv.w;
            }
        }
        #pragma unroll
        for (int n = 0; n < NHx; n++) {
            float s = acc[n];
            #pragma unroll
            for (int o = 16; o; o >>= 1) s += __shfl_xor_sync(0xffffffffu, s, o);
            if (lane == 0)
                sc[((size_t)(b * NHx + n)) * Sx + j] = s * 0.0883883476483184f;
        }
    }
}

__global__ __launch_bounds__(256) void softmax_k(float* __restrict__ sc)
{
    int row = blockIdx.x;
    float4* p = (float4*)(sc + (size_t)row * Sx);
    int t = threadIdx.x;
    float4 v = p[t];
    __shared__ float sh[8];

    float m = fmaxf(fmaxf(v.x, v.y), fmaxf(v.z, v.w));
    #pragma unroll
    for (int o = 16; o; o >>= 1) m = fmaxf(m, __shfl_xor_sync(0xffffffffu, m, o));
    if ((t & 31) == 0) sh[t >> 5] = m;
    __syncthreads();
    m = sh[0];
    #pragma unroll
    for (int i = 1; i < 8; i++) m = fmaxf(m, sh[i]);

    v.x = __expf(v.x - m); v.y = __expf(v.y - m);
    v.z = __expf(v.z - m); v.w = __expf(v.w - m);
    float sum = v.x + v.y + v.z + v.w;
    #pragma unroll
    for (int o = 16; o; o >>= 1) sum += __shfl_xor_sync(0xffffffffu, sum, o);
    __syncthreads();
    if ((t & 31) == 0) sh[t >> 5] = sum;
    __syncthreads();
    sum = 0.f;
    #pragma unroll
    for (int i = 0; i < 8; i++) sum += sh[i];
    float inv = 1.f / sum;
    v.x *= inv; v.y *= inv; v.z *= inv; v.w *= inv;
    p[t] = v;
}

__global__ __launch_bounds__(128) void wsum_k(
    const float* __restrict__ X, const float* __restrict__ sc,
    float* __restrict__ wp)
{
    int b = blockIdx.x, mt = blockIdx.y, jg = blockIdx.z;
    int m = mt * 128 + threadIdx.x;
    __shared__ float as[NHx][128];
    for (int i = threadIdx.x; i < NHx * 128; i += 128)
        as[i >> 7][i & 127] =
            sc[((size_t)(b * NHx + (i >> 7))) * Sx + jg * 128 + (i & 127)];
    __syncthreads();
    float acc[NHx] = {0.f, 0.f, 0.f, 0.f, 0.f, 0.f, 0.f, 0.f};
    const float* xp = X + ((size_t)b * Sx + jg * 128) * Hx + m;
    #pragma unroll 4
    for (int jj = 0; jj < 128; jj++) {
        float xv = xp[(size_t)jj * Hx];
        #pragma unroll
        for (int n = 0; n < NHx; n++) acc[n] = fmaf(as[n][jj], xv, acc[n]);
    }
    #pragma unroll
    for (int n = 0; n < NHx; n++)
        wp[(((size_t)jg * Bx + b) * NHx + n) * Hx + m] = acc[n];
}

__global__ void wred_k(const float* __restrict__ wp, float* __restrict__ w)
{
    int i = blockIdx.x * blockDim.x + threadIdx.x;  // < Bx*NHx*Hx
    float s = 0.f;
    #pragma unroll
    for (int jg = 0; jg < JG; jg++)
        s += wp[(size_t)jg * (Bx * NHx * Hx) + i];
    w[i] = s;
}

__global__ void ov_k(const float* __restrict__ w, const float* __restrict__ inw,
                     const float* __restrict__ inb, float* __restrict__ o)
{
    int gw = (blockIdx.x * blockDim.x + threadIdx.x) >> 5;
    int lane = threadIdx.x & 31;
    if (gw >= Bx * Hx) return;
    int hd = gw & (Hx - 1), b = gw >> 10;
    int n = hd >> 7;
    const float4* wr = (const float4*)(w + ((size_t)(b * NHx + n)) * Hx);
    const float4* vr = (const float4*)(inw + ((size_t)(2 * Hx + hd)) * Hx);
    float s = 0.f;
    #pragma unroll
    for (int k = lane; k < Hx / 4; k += 32) {
        float4 a = wr[k], c = vr[k];
        s += a.x * c.x + a.y * c.y + a.z * c.z + a.w * c.w;
    }
    #pragma unroll
    for (int o2 = 16; o2; o2 >>= 1) s += __shfl_xor_sync(0xffffffffu, s, o2);
    if (lane == 0) o[(size_t)b * Hx + hd] = s + inb[2 * Hx + hd];
}

// ---------------- launch orchestration -------------------------------------
extern "C" void kernel_launch(void* const* d_in, const int* in_sizes, int n_in,
                              void* d_out, int out_size)
{
    const float* x    = (const float*)d_in[0];
    const float* Wf   = (const float*)d_in[1];
    const float* bf   = (const float*)d_in[2];
    const float* Wi   = (const float*)d_in[3];
    const float* bi   = (const float*)d_in[4];
    const float* Wh   = (const float*)d_in[5];
    const float* bh   = (const float*)d_in[6];
    const float* inw  = (const float*)d_in[7];
    const float* inb  = (const float*)d_in[8];
    const float* outw = (const float*)d_in[9];
    const float* outb = (const float*)d_in[10];
    const float* fcw  = (const float*)d_in[11];
    const float* fcb  = (const float*)d_in[12];
    float* out = (float*)d_out;

    float *bufA, *bufF, *bufI, *bufH, *chP, *chQ, *chS;
    float *scoresP, *qP, *uP, *wpP, *wP, *oP, *lastP;
    __half *WHp, *WLp, *AHp;
    cudaGetSymbolAddress((void**)&bufA, g_bufA);
    cudaGetSymbolAddress((void**)&bufF, g_bufF);
    cudaGetSymbolAddress((void**)&bufI, g_bufI);
    cudaGetSymbolAddress((void**)&bufH, g_bufH);
    cudaGetSymbolAddress((void**)&chP, g_chP);
    cudaGetSymbolAddress((void**)&chQ, g_chQ);
    cudaGetSymbolAddress((void**)&chS, g_chS);
    cudaGetSymbolAddress((void**)&scoresP, g_scores);
    cudaGetSymbolAddress((void**)&qP, g_q);
    cudaGetSymbolAddress((void**)&uP, g_u);
    cudaGetSymbolAddress((void**)&wpP, g_wp);
    cudaGetSymbolAddress((void**)&wP, g_w);
    cudaGetSymbolAddress((void**)&oP, g_o);
    cudaGetSymbolAddress((void**)&lastP, g_last);
    cudaGetSymbolAddress((void**)&WHp, g_WH);
    cudaGetSymbolAddress((void**)&WLp, g_WL);
    cudaGetSymbolAddress((void**)&AHp, g_AH);

    static int smemSet = 0;
    if (!smemSet) {
        cudaFuncSetAttribute(hgemm_fused_k,
                             cudaFuncAttributeMaxDynamicSharedMemorySize, SMEMB);
        smemSet = 1;
    }

    // ---- conversions: gate weights hi only; h~ weights hi+lo; x hi only
    conv_k<<<NWF / 4 / 256, 256>>>(Wf, WHp,           nullptr,       NWF, 0);
    conv_k<<<NWF / 4 / 256, 256>>>(Wi, WHp + NWF,     nullptr,       NWF, 0);
    conv_k<<<NWF / 4 / 256, 256>>>(Wh, WHp + 2 * NWF, WLp + 2 * NWF, NWF, 1);
    conv_k<<<(Mx * Hx) / 4 / 256, 256>>>(x, AHp, nullptr, Mx * Hx, 0);

    dim3 gl(24, 128);                 // fused f,i,h GEMM
    const int scanT = Bx * CC * Hx;   // 512K threads

    for (int l = 0; l < Lx; l++) {
        size_t wo = (size_t)l * Hx * Hx;
        GemmArgs ga;
        ga.WH[0] = WHp + wo;           ga.WL[0] = nullptr;
        ga.WH[1] = WHp + NWF + wo;     ga.WL[1] = nullptr;
        ga.WH[2] = WHp + 2 * NWF + wo; ga.WL[2] = WLp + 2 * NWF + wo;
        ga.bias[0] = bf + (size_t)l * Hx;
        ga.bias[1] = bi + (size_t)l * Hx;
        ga.bias[2] = bh + (size_t)l * Hx;
        ga.C[0] = bufF; ga.C[1] = bufI; ga.C[2] = bufH;
        ga.hlMask = 0x4;   // hi*lo only for h_tilde
        ga.lhMask = 0x0;
        hgemm_fused_k<<<gl, 256, SMEMB>>>(AHp, AHp, ga);
        scan_p1<<<scanT / 256, 256>>>(bufF, bufI, bufH, bufF, bufI, chP, chQ);
        scan_p2<<<(Bx * Hx) / 256, 256>>>(chP, chQ, chS);
        scan_p3<<<scanT / 256, 256>>>(bufF, bufI, chS, bufA, AHp,
                                      (l == Lx - 1) ? 1 : 0,
                                      (l == Lx - 1) ? 0 : 1);
    }

    // ---- attention on last query row via pullback (exact fp32)
    vecmat_k<<<(Bx * Hx * 32 + 255) / 256, 256>>>(
        bufA + (size_t)(Sx - 1) * Hx, Sx * Hx, inw, inb, nullptr, 0, qP, Bx, Hx);
    ku_k<<<Bx * NHx, 256>>>(qP, inw, uP);
    scores2_k<<<Bx * 16, 256>>>(bufA, uP, scoresP);
    softmax_k<<<Bx * NHx, 256>>>(scoresP);
    wsum_k<<<dim3(Bx, 8, JG), 128>>>(bufA, scoresP, wpP);
    wred_k<<<(Bx * NHx * Hx) / 256, 256>>>(wpP, wP);
    ov_k<<<(Bx * Hx * 32 + 255) / 256, 256>>>(wP, inw, inb, oP);

    // ---- out-proj + residual (last token), then fc head
    vecmat_k<<<(Bx * Hx * 32 + 255) / 256, 256>>>(
        oP, Hx, outw, outb, bufA + (size_t)(Sx - 1) * Hx, Sx * Hx, lastP, Bx, Hx);
    vecmat_k<<<(Bx * Ox * 32 + 255) / 256, 256>>>(
        lastP, Hx, fcw, fcb, nullptr, 0, out, Bx, Ox);
}

// round 9
// speedup vs baseline: 7.9510x; 1.5000x over previous
#include <cuda_runtime.h>
#include <cuda_fp16.h>
#include <math.h>
#include <stdint.h>

// Problem constants
#define Bx  16
#define Sx  1024
#define Hx  1024
#define Ox  256
#define Lx  4
#define NHx 8
#define DHx 128
#define Mx  (Bx*Sx)   // 16384 rows
#define CT  32        // scan chunk length
#define CC  (Sx/CT)   // 32 chunks
#define JG  8         // wsum j-split

typedef unsigned long long u64;

// ---------------- scratch (device globals: no allocation allowed) ----------
__device__ float g_bufA[(size_t)Mx * Hx];
__device__ float g_bufF[(size_t)Mx * Hx];
__device__ float g_bufI[(size_t)Mx * Hx];
__device__ float g_bufH[(size_t)Mx * Hx];
__device__ float g_chP[Bx * Hx * CC];
__device__ float g_chQ[Bx * Hx * CC];
__device__ float g_chS[Bx * Hx * CC];
__device__ float g_scores[Bx * NHx * Sx];
__device__ float g_q[Bx * Hx];
__device__ float g_u[Bx * NHx * Hx];           // Wk^T q per (b,head)
__device__ float g_wp[JG * Bx * NHx * Hx];     // partial weighted sums
__device__ float g_w[Bx * NHx * Hx];           // reduced weighted sums
__device__ float g_o[Bx * Hx];
__device__ float g_last[Bx * Hx];

// fp16 buffers (LSTM weights + activations, hi part only — pure fp16 GEMM)
#define NWF 4194304          // one gate's weights over 4 layers
#define NWTOT (3*NWF)
__device__ __half g_WH[NWTOT];
__device__ __half g_AH[(size_t)Mx * Hx];

// ======================= helpers ===========================================
__device__ __forceinline__ uint32_t smem_u32(const void* p) {
    uint32_t a;
    asm("{ .reg .u64 t; cvta.to.shared.u64 t, %1; cvt.u32.u64 %0, t; }"
        : "=r"(a) : "l"(p));
    return a;
}
__device__ __forceinline__ void cpa16(uint32_t dst, const void* src) {
    asm volatile("cp.async.cg.shared.global [%0], [%1], 16;" :: "r"(dst), "l"(src));
}
__device__ __forceinline__ void ldm4(uint32_t& r0, uint32_t& r1,
                                     uint32_t& r2, uint32_t& r3, uint32_t a) {
    asm volatile("ldmatrix.sync.aligned.m8n8.x4.shared.b16 {%0,%1,%2,%3}, [%4];"
        : "=r"(r0), "=r"(r1), "=r"(r2), "=r"(r3) : "r"(a));
}
__device__ __forceinline__ void mma16816(float* d, const uint32_t* a, const uint32_t* b) {
    asm volatile("mma.sync.aligned.m16n8k16.row.col.f32.f16.f16.f32 "
        "{%0,%1,%2,%3}, {%4,%5,%6,%7}, {%8,%9}, {%0,%1,%2,%3};"
        : "+f"(d[0]), "+f"(d[1]), "+f"(d[2]), "+f"(d[3])
        : "r"(a[0]), "r"(a[1]), "r"(a[2]), "r"(a[3]), "r"(b[0]), "r"(b[1]));
}
__device__ __forceinline__ float fast_rcp(float x) {
    float r; asm("rcp.approx.f32 %0, %1;" : "=f"(r) : "f"(x)); return r;
}

// ======================= fused multi-output pure-fp16 HGEMM ================
// region = blockIdx.x >> 3 selects (W, bias, C). One hh product per region.
struct GemmArgs {
    const __half* WH[3];
    const float*  bias[3];
    float*        C[3];
};

#define STG_SZ 16384
#define T_A 0
#define T_B 8192
#define SMEMB (3 * STG_SZ)   // 48 KB

__global__ __launch_bounds__(256) void hgemm_fused_k(
    const __half* __restrict__ AH, GemmArgs ga)
{
    extern __shared__ __align__(1024) char smem[];
    const uint32_t sb = smem_u32(smem);
    const int tid = threadIdx.x;
    const int wid = tid >> 5, lane = tid & 31;
    const int region = blockIdx.x >> 3;
    const int bx = blockIdx.x & 7;
    const int by = blockIdx.y;

    const __half* WH = ga.WH[region];
    const float*  bias = ga.bias[region];
    float*        C = ga.C[region];

    const int lm  = tid >> 1;
    const int lc0 = (tid & 1) * 2;
    const size_t aoff = (size_t)(by * 128 + lm) * Hx;
    const size_t boff = (size_t)(bx * 128 + lm) * Hx;
    const int sws = (lm >> 1) & 3;
    const uint32_t d0 = lm * 64 + 16 * (lc0 ^ sws);
    const uint32_t d1 = lm * 64 + 16 * ((lc0 + 1) ^ sws);
    const int g0 = 8 * lc0, g1 = 8 * (lc0 + 1);

    #define LOAD_CHUNK(k0, s) do {                                          \
        uint32_t st_ = sb + (s) * STG_SZ;                                   \
        cpa16(st_ + T_A + d0, AH + aoff + (k0) + g0);                       \
        cpa16(st_ + T_A + d1, AH + aoff + (k0) + g1);                       \
        cpa16(st_ + T_B + d0, WH + boff + (k0) + g0);                       \
        cpa16(st_ + T_B + d1, WH + boff + (k0) + g1);                       \
        asm volatile("cp.async.commit_group;" ::: "memory");                \
    } while (0)

    const int wm = (wid & 3) * 32;
    const int wn = (wid >> 2) * 64;
    const int ar0 = wm + (lane & 15);
    const int aK  = (lane >> 4) & 1;
    const int bK  = (lane >> 3) & 1;
    const int bnh = (lane >> 4) & 1;
    const int br0 = wn + (lane & 7);

    float acc[2][8][4];
    #pragma unroll
    for (int i = 0; i < 2; i++)
        #pragma unroll
        for (int j = 0; j < 8; j++)
            #pragma unroll
            for (int q = 0; q < 4; q++)
                acc[i][j][q] = 0.f;

    LOAD_CHUNK(0, 0);
    LOAD_CHUNK(32, 1);

    for (int c = 0; c < 32; c++) {
        const int s = c % 3;
        if (c < 31) asm volatile("cp.async.wait_group 1;" ::: "memory");
        else        asm volatile("cp.async.wait_group 0;" ::: "memory");
        __syncthreads();
        if (c + 2 < 32) LOAD_CHUNK((c + 2) * 32, (c + 2) % 3);

        const uint32_t st = sb + s * STG_SZ;
        #pragma unroll
        for (int kk = 0; kk < 2; kk++) {
            uint32_t ah[2][4], bh[8][2];
            #pragma unroll
            for (int mt = 0; mt < 2; mt++) {
                const int row = ar0 + mt * 16;
                const uint32_t off = (uint32_t)(row * 64
                                   + 16 * ((kk * 2 + aK) ^ ((row >> 1) & 3)));
                ldm4(ah[mt][0], ah[mt][1], ah[mt][2], ah[mt][3], st + T_A + off);
            }
            #pragma unroll
            for (int p = 0; p < 4; p++) {
                const int row = br0 + (p * 2 + bnh) * 8;
                const uint32_t off = (uint32_t)(row * 64
                                   + 16 * ((kk * 2 + bK) ^ ((row >> 1) & 3)));
                ldm4(bh[2*p][0], bh[2*p][1], bh[2*p+1][0], bh[2*p+1][1], st + T_B + off);
            }
            #pragma unroll
            for (int mt = 0; mt < 2; mt++)
                #pragma unroll
                for (int nt = 0; nt < 8; nt++)
                    mma16816(acc[mt][nt], ah[mt], bh[nt]);
        }
    }

    const int r0 = lane >> 2;
    const int cc = (lane & 3) * 2;
    #pragma unroll
    for (int mt = 0; mt < 2; mt++) {
        const int mrow = by * 128 + wm + mt * 16 + r0;
        #pragma unroll
        for (int nt = 0; nt < 8; nt++) {
            const int col = bx * 128 + wn + nt * 8 + cc;
            const float b0 = bias[col], b1 = bias[col + 1];
            float2 v0 = {acc[mt][nt][0] + b0, acc[mt][nt][1] + b1};
            float2 v1 = {acc[mt][nt][2] + b0, acc[mt][nt][3] + b1};
            *(float2*)&C[(size_t)mrow * Hx + col]       = v0;
            *(float2*)&C[(size_t)(mrow + 8) * Hx + col] = v1;
        }
    }
}

// ---------------- fp32 -> f16 conversion -----------------------------------
__global__ __launch_bounds__(256) void conv_k(
    const float* __restrict__ src, __half* __restrict__ hi, int n)
{
    int i = blockIdx.x * blockDim.x + threadIdx.x;
    if (i >= n / 4) return;
    float4 v = ((const float4*)src)[i];
    __half2* hp = (__half2*)hi;
    hp[i * 2]     = __halves2half2(__float2half_rn(v.x), __float2half_rn(v.y));
    hp[i * 2 + 1] = __halves2half2(__float2half_rn(v.z), __float2half_rn(v.w));
}

// ---------------- chunked minLSTM scan -------------------------------------
__global__ __launch_bounds__(256) void scan_p1(
    const float* __restrict__ F, const float* __restrict__ I,
    const float* __restrict__ Ht, float* __restrict__ P, float* __restrict__ Q,
    float* __restrict__ chP, float* __restrict__ chQ)
{
    int t = blockIdx.x * blockDim.x + threadIdx.x;
    int h = t & (Hx - 1);
    int bc = t >> 10;
    int c = bc & (CC - 1);
    int b = bc >> 5;
    size_t base = ((size_t)b * Sx + (size_t)c * CT) * Hx + h;
    float accP = 1.f, accQ = 0.f;
    #pragma unroll 4
    for (int s = 0; s < CT; s++) {
        size_t idx = base + (size_t)s * Hx;
        float ea = __expf(F[idx]);
        float eb = __expf(I[idx]);
        float hv = Ht[idx];
        float na = ea * (1.f + eb);
        float nb = eb * (1.f + ea);
        float r = fast_rcp(na + nb);
        float p = na * r;
        float q = nb * r * hv;
        P[idx] = p; Q[idx] = q;
        accQ = fmaf(p, accQ, q);
        accP *= p;
    }
    chP[t] = accP;
    chQ[t] = accQ;
}

__global__ __launch_bounds__(256) void scan_p2(
    const float* __restrict__ chP, const float* __restrict__ chQ,
    float* __restrict__ chS)
{
    int u = blockIdx.x * blockDim.x + threadIdx.x;
    int h = u & (Hx - 1);
    int b = u >> 10;
    float hc = 0.f;
    #pragma unroll
    for (int c = 0; c < CC; c++) {
        size_t idx = ((size_t)b * CC + c) * Hx + h;
        chS[idx] = hc;
        hc = fmaf(chP[idx], hc, chQ[idx]);
    }
}

// pass3: apply scan. writeOut -> fp32 Out (last layer only),
// writeAH -> f16 (feeds next layer's GEMM).
__global__ __launch_bounds__(256) void scan_p3(
    const float* __restrict__ P, const float* __restrict__ Q,
    const float* __restrict__ chS, float* __restrict__ Out,
    __half* __restrict__ OH, int writeOut, int writeAH)
{
    int t = blockIdx.x * blockDim.x + threadIdx.x;
    int h = t & (Hx - 1);
    int bc = t >> 10;
    int c = bc & (CC - 1);
    int b = bc >> 5;
    size_t base = ((size_t)b * Sx + (size_t)c * CT) * Hx + h;
    float hp = chS[t];
    #pragma unroll 4
    for (int s = 0; s < CT; s++) {
        size_t idx = base + (size_t)s * Hx;
        hp = fmaf(P[idx], hp, Q[idx]);
        if (writeOut) Out[idx] = hp;
        if (writeAH)  OH[idx] = __float2half_rn(hp);
    }
}

// ---------------- small vec-mat --------------------------------------------
__global__ void vecmat_k(const float* __restrict__ X, int xStride,
                         const float* __restrict__ W, const float* __restrict__ bias,
                         const float* __restrict__ res, int resStride,
                         float* __restrict__ out, int Bn, int N)
{
    int gw = (blockIdx.x * blockDim.x + threadIdx.x) >> 5;
    int lane = threadIdx.x & 31;
    if (gw >= Bn * N) return;
    int b = gw / N, n = gw % N;
    const float* xr = X + (size_t)b * xStride;
    const float* wr = W + (size_t)n * Hx;
    float s = 0.f;
    #pragma unroll
    for (int k = lane * 4; k < Hx; k += 128) {
        float4 xv = *(const float4*)(xr + k);
        float4 wv = *(const float4*)(wr + k);
        s += xv.x * wv.x + xv.y * wv.y + xv.z * wv.z + xv.w * wv.w;
    }
    #pragma unroll
    for (int o = 16; o; o >>= 1) s += __shfl_xor_sync(0xffffffffu, s, o);
    if (lane == 0) {
        float v = s + bias[n];
        if (res) v += res[(size_t)b * resStride + n];
        out[(size_t)b * N + n] = v;
    }
}

// ---------------- attention via projection pullback ------------------------
__global__ __launch_bounds__(256) void ku_k(
    const float* __restrict__ q, const float* __restrict__ inw,
    float* __restrict__ u)
{
    int bn = blockIdx.x;           // b*8+n
    int n = bn & (NHx - 1), b = bn >> 3;
    __shared__ float qs[DHx];
    if (threadIdx.x < DHx) qs[threadIdx.x] = q[(size_t)b * Hx + n * DHx + threadIdx.x];
    __syncthreads();
    const float* Wk = inw + ((size_t)Hx + (size_t)n * DHx) * Hx;
    #pragma unroll
    for (int m0 = 0; m0 < Hx; m0 += 256) {
        int m = m0 + threadIdx.x;
        float acc = 0.f;
        #pragma unroll 8
        for (int hd = 0; hd < DHx; hd++)
            acc = fmaf(qs[hd], Wk[(size_t)hd * Hx + m], acc);
        u[(size_t)bn * Hx + m] = acc;
    }
}

__global__ __launch_bounds__(256) void scores2_k(
    const float* __restrict__ X, const float* __restrict__ u,
    float* __restrict__ sc)
{
    int b = blockIdx.x >> 4;
    int jt = blockIdx.x & 15;      // j-tile of 64
    __shared__ float us[NHx][Hx];  // 32KB
    for (int i = threadIdx.x; i < NHx * Hx; i += 256)
        us[i >> 10][i & (Hx - 1)] = u[(size_t)b * NHx * Hx + i];
    __syncthreads();
    int wid = threadIdx.x >> 5, lane = threadIdx.x & 31;
    #pragma unroll
    for (int jj = 0; jj < 8; jj++) {
        int j = jt * 64 + wid * 8 + jj;
        const float4* xr = (const float4*)(X + ((size_t)b * Sx + j) * Hx);
        float acc[NHx] = {0.f, 0.f, 0.f, 0.f, 0.f, 0.f, 0.f, 0.f};
        for (int k = lane; k < Hx / 4; k += 32) {
            float4 xv = xr[k];
            #pragma unroll
            for (int n = 0; n < NHx; n++) {
                float4 uv = *(const float4*)&us[n][k * 4];
                acc[n] += xv.x * uv.x + xv.y * uv.y + xv.z * uv.z + xv.w * uv.w;
            }
        }
        #pragma unroll
        for (int n = 0; n < NHx; n++) {
            float s = acc[n];
            #pragma unroll
            for (int o = 16; o; o >>= 1) s += __shfl_xor_sync(0xffffffffu, s, o);
            if (lane == 0)
                sc[((size_t)(b * NHx + n)) * Sx + j] = s * 0.0883883476483184f;
        }
    }
}

__global__ __launch_bounds__(256) void softmax_k(float* __restrict__ sc)
{
    int row = blockIdx.x;
    float4* p = (float4*)(sc + (size_t)row * Sx);
    int t = threadIdx.x;
    float4 v = p[t];
    __shared__ float sh[8];

    float m = fmaxf(fmaxf(v.x, v.y), fmaxf(v.z, v.w));
    #pragma unroll
    for (int o = 16; o; o >>= 1) m = fmaxf(m, __shfl_xor_sync(0xffffffffu, m, o));
    if ((t & 31) == 0) sh[t >> 5] = m;
    __syncthreads();
    m = sh[0];
    #pragma unroll
    for (int i = 1; i < 8; i++) m = fmaxf(m, sh[i]);

    v.x = __expf(v.x - m); v.y = __expf(v.y - m);
    v.z = __expf(v.z - m); v.w = __expf(v.w - m);
    float sum = v.x + v.y + v.z + v.w;
    #pragma unroll
    for (int o = 16; o; o >>= 1) sum += __shfl_xor_sync(0xffffffffu, sum, o);
    __syncthreads();
    if ((t & 31) == 0) sh[t >> 5] = sum;
    __syncthreads();
    sum = 0.f;
    #pragma unroll
    for (int i = 0; i < 8; i++) sum += sh[i];
    float inv = 1.f / sum;
    v.x *= inv; v.y *= inv; v.z *= inv; v.w *= inv;
    p[t] = v;
}

__global__ __launch_bounds__(128) void wsum_k(
    const float* __restrict__ X, const float* __restrict__ sc,
    float* __restrict__ wp)
{
    int b = blockIdx.x, mt = blockIdx.y, jg = blockIdx.z;
    int m = mt * 128 + threadIdx.x;
    __shared__ float as[NHx][128];
    for (int i = threadIdx.x; i < NHx * 128; i += 128)
        as[i >> 7][i & 127] =
            sc[((size_t)(b * NHx + (i >> 7))) * Sx + jg * 128 + (i & 127)];
    __syncthreads();
    float acc[NHx] = {0.f, 0.f, 0.f, 0.f, 0.f, 0.f, 0.f, 0.f};
    const float* xp = X + ((size_t)b * Sx + jg * 128) * Hx + m;
    #pragma unroll 4
    for (int jj = 0; jj < 128; jj++) {
        float xv = xp[(size_t)jj * Hx];
        #pragma unroll
        for (int n = 0; n < NHx; n++) acc[n] = fmaf(as[n][jj], xv, acc[n]);
    }
    #pragma unroll
    for (int n = 0; n < NHx; n++)
        wp[(((size_t)jg * Bx + b) * NHx + n) * Hx + m] = acc[n];
}

__global__ void wred_k(const float* __restrict__ wp, float* __restrict__ w)
{
    int i = blockIdx.x * blockDim.x + threadIdx.x;  // < Bx*NHx*Hx
    float s = 0.f;
    #pragma unroll
    for (int jg = 0; jg < JG; jg++)
        s += wp[(size_t)jg * (Bx * NHx * Hx) + i];
    w[i] = s;
}

__global__ void ov_k(const float* __restrict__ w, const float* __restrict__ inw,
                     const float* __restrict__ inb, float* __restrict__ o)
{
    int gw = (blockIdx.x * blockDim.x + threadIdx.x) >> 5;
    int lane = threadIdx.x & 31;
    if (gw >= Bx * Hx) return;
    int hd = gw & (Hx - 1), b = gw >> 10;
    int n = hd >> 7;
    const float4* wr = (const float4*)(w + ((size_t)(b * NHx + n)) * Hx);
    const float4* vr = (const float4*)(inw + ((size_t)(2 * Hx + hd)) * Hx);
    float s = 0.f;
    #pragma unroll
    for (int k = lane; k < Hx / 4; k += 32) {
        float4 a = wr[k], c = vr[k];
        s += a.x * c.x + a.y * c.y + a.z * c.z + a.w * c.w;
    }
    #pragma unroll
    for (int o2 = 16; o2; o2 >>= 1) s += __shfl_xor_sync(0xffffffffu, s, o2);
    if (lane == 0) o[(size_t)b * Hx + hd] = s + inb[2 * Hx + hd];
}

// ---------------- launch orchestration -------------------------------------
extern "C" void kernel_launch(void* const* d_in, const int* in_sizes, int n_in,
                              void* d_out, int out_size)
{
    const float* x    = (const float*)d_in[0];
    const float* Wf   = (const float*)d_in[1];
    const float* bf   = (const float*)d_in[2];
    const float* Wi   = (const float*)d_in[3];
    const float* bi   = (const float*)d_in[4];
    const float* Wh   = (const float*)d_in[5];
    const float* bh   = (const float*)d_in[6];
    const float* inw  = (const float*)d_in[7];
    const float* inb  = (const float*)d_in[8];
    const float* outw = (const float*)d_in[9];
    const float* outb = (const float*)d_in[10];
    const float* fcw  = (const float*)d_in[11];
    const float* fcb  = (const float*)d_in[12];
    float* out = (float*)d_out;

    float *bufA, *bufF, *bufI, *bufH, *chP, *chQ, *chS;
    float *scoresP, *qP, *uP, *wpP, *wP, *oP, *lastP;
    __half *WHp, *AHp;
    cudaGetSymbolAddress((void**)&bufA, g_bufA);
    cudaGetSymbolAddress((void**)&bufF, g_bufF);
    cudaGetSymbolAddress((void**)&bufI, g_bufI);
    cudaGetSymbolAddress((void**)&bufH, g_bufH);
    cudaGetSymbolAddress((void**)&chP, g_chP);
    cudaGetSymbolAddress((void**)&chQ, g_chQ);
    cudaGetSymbolAddress((void**)&chS, g_chS);
    cudaGetSymbolAddress((void**)&scoresP, g_scores);
    cudaGetSymbolAddress((void**)&qP, g_q);
    cudaGetSymbolAddress((void**)&uP, g_u);
    cudaGetSymbolAddress((void**)&wpP, g_wp);
    cudaGetSymbolAddress((void**)&wP, g_w);
    cudaGetSymbolAddress((void**)&oP, g_o);
    cudaGetSymbolAddress((void**)&lastP, g_last);
    cudaGetSymbolAddress((void**)&WHp, g_WH);
    cudaGetSymbolAddress((void**)&AHp, g_AH);

    static int smemSet = 0;
    if (!smemSet) {
        cudaFuncSetAttribute(hgemm_fused_k,
                             cudaFuncAttributeMaxDynamicSharedMemorySize, SMEMB);
        smemSet = 1;
    }

    // ---- conversions: weights + layer-0 activations (fp16 hi only)
    conv_k<<<NWF / 4 / 256, 256>>>(Wf, WHp,           NWF);
    conv_k<<<NWF / 4 / 256, 256>>>(Wi, WHp + NWF,     NWF);
    conv_k<<<NWF / 4 / 256, 256>>>(Wh, WHp + 2 * NWF, NWF);
    conv_k<<<(Mx * Hx) / 4 / 256, 256>>>(x, AHp, Mx * Hx);

    dim3 gl(24, 128);                 // fused f,i,h GEMM
    const int scanT = Bx * CC * Hx;   // 512K threads

    for (int l = 0; l < Lx; l++) {
        size_t wo = (size_t)l * Hx * Hx;
        GemmArgs ga;
        ga.WH[0] = WHp + wo;
        ga.WH[1] = WHp + NWF + wo;
        ga.WH[2] = WHp + 2 * NWF + wo;
        ga.bias[0] = bf + (size_t)l * Hx;
        ga.bias[1] = bi + (size_t)l * Hx;
        ga.bias[2] = bh + (size_t)l * Hx;
        ga.C[0] = bufF; ga.C[1] = bufI; ga.C[2] = bufH;
        hgemm_fused_k<<<gl, 256, SMEMB>>>(AHp, ga);
        scan_p1<<<scanT / 256, 256>>>(bufF, bufI, bufH, bufF, bufI, chP, chQ);
        scan_p2<<<(Bx * Hx) / 256, 256>>>(chP, chQ, chS);
        scan_p3<<<scanT / 256, 256>>>(bufF, bufI, chS, bufA, AHp,
                                      (l == Lx - 1) ? 1 : 0,
                                      (l == Lx - 1) ? 0 : 1);
    }

    // ---- attention on last query row via pullback (exact fp32)
    vecmat_k<<<(Bx * Hx * 32 + 255) / 256, 256>>>(
        bufA + (size_t)(Sx - 1) * Hx, Sx * Hx, inw, inb, nullptr, 0, qP, Bx, Hx);
    ku_k<<<Bx * NHx, 256>>>(qP, inw, uP);
    scores2_k<<<Bx * 16, 256>>>(bufA, uP, scoresP);
    softmax_k<<<Bx * NHx, 256>>>(scoresP);
    wsum_k<<<dim3(Bx, 8, JG), 128>>>(bufA, scoresP, wpP);
    wred_k<<<(Bx * NHx * Hx) / 256, 256>>>(wpP, wP);
    ov_k<<<(Bx * Hx * 32 + 255) / 256, 256>>>(wP, inw, inb, oP);

    // ---- out-proj + residual (last token), then fc head
    vecmat_k<<<(Bx * Hx * 32 + 255) / 256, 256>>>(
        oP, Hx, outw, outb, bufA + (size_t)(Sx - 1) * Hx, Sx * Hx, lastP, Bx, Hx);
    vecmat_k<<<(Bx * Ox * 32 + 255) / 256, 256>>>(
        lastP, Hx, fcw, fcb, nullptr, 0, out, Bx, Ox);
}